// round 6
// baseline (speedup 1.0000x reference)
#include <cuda_runtime.h>
#include <cuda_fp16.h>
#include <cstdint>

// ============================================================================
// B=512, D=256, H=512
//   yi = h@W1[:D]+b1 ; yj = h@W1[D:]
//   x = tanh(yi[i]+yj[j]); z = tanh(x@W2+b2); logits = z@W3+b3, diag=-20
// Toolchain note: harness emits compute_103 PTX (no 'a'), so tcgen05 is
// unavailable. Use baseline mma.sync.m16n8k16.f16 + ldmatrix + cp.async.
// ============================================================================

#define NB 512
#define ND 256
#define NH 512

// -------------------- device scratch ----------------------------------------
__device__ __align__(16) float  g_yi[NB * NH];      // yi + b1 folded
__device__ __align__(16) float  g_yj[NB * NH];
__device__ __align__(16) __half g_w2h[NH * NH];     // W2h[n][k] = (half)W2[k][n]
__device__ __align__(16) float  g_part[2 * NB * NB];

// -------------------- helpers -----------------------------------------------
__device__ __forceinline__ uint32_t smem_u32(const void* p) {
    uint32_t a;
    asm("{ .reg .u64 t; cvta.to.shared.u64 t, %1; cvt.u32.u64 %0, t; }"
        : "=r"(a) : "l"(p));
    return a;
}

#define SWZ(o) ((o) ^ (((o) >> 3) & 0x70))

#define LDSM4(r, addr) \
    asm volatile("ldmatrix.sync.aligned.m8n8.x4.shared.b16 {%0,%1,%2,%3}, [%4];" \
                 : "=r"((r)[0]), "=r"((r)[1]), "=r"((r)[2]), "=r"((r)[3]) \
                 : "r"(addr))

#define MMA16816(d, a, b0, b1) \
    asm volatile("mma.sync.aligned.m16n8k16.row.col.f32.f16.f16.f32 " \
                 "{%0,%1,%2,%3}, {%4,%5,%6,%7}, {%8,%9}, {%0,%1,%2,%3};" \
                 : "+f"((d)[0]), "+f"((d)[1]), "+f"((d)[2]), "+f"((d)[3]) \
                 : "r"((a)[0]), "r"((a)[1]), "r"((a)[2]), "r"((a)[3]), \
                   "r"(b0), "r"(b1))

#define CP_ASYNC16(dst, src) \
    asm volatile("cp.async.cg.shared.global [%0], [%1], 16;" :: "r"(dst), "l"(src))
#define CP_COMMIT()  asm volatile("cp.async.commit_group;" ::: "memory")
#define CP_WAIT0()   asm volatile("cp.async.wait_group 0;" ::: "memory")

// Accurate tanh: (e^{2x}-1)/(e^{2x}+1), 2 MUFU (EX2 + RCP), few-ulp error.
__device__ __forceinline__ float ftanh(float x) {
    x = fminf(fmaxf(x, -15.0f), 15.0f);
    float e = __expf(2.0f * x);
    return __fdividef(e - 1.0f, e + 1.0f);
}

// ============================================================================
// Stage A1: yi = h@W1[:D]+b1 (z=0), yj = h@W1[D:] (z=1)
// ============================================================================
__global__ void k_gemm1(const float* __restrict__ h, const float* __restrict__ W1,
                        const float* __restrict__ b1) {
    __shared__ float hs[16][16];
    __shared__ float ws[16][17];
    int tx = threadIdx.x, ty = threadIdx.y;
    int row = blockIdx.y * 16 + ty;   // i
    int col = blockIdx.x * 16 + tx;   // n
    int base = blockIdx.z * ND;
    float acc = (blockIdx.z == 0) ? b1[col] : 0.0f;
    for (int kt = 0; kt < ND; kt += 16) {
        hs[ty][tx] = h[row * ND + kt + tx];
        ws[ty][tx] = W1[(base + kt + ty) * NH + col];
        __syncthreads();
#pragma unroll
        for (int q = 0; q < 16; q++) acc = fmaf(hs[ty][q], ws[q][tx], acc);
        __syncthreads();
    }
    (blockIdx.z ? g_yj : g_yi)[row * NH + col] = acc;
}

// ============================================================================
// Stage A2: W2h[n][k] = half(W2[k][n])
// ============================================================================
__global__ void k_w2half(const float* __restrict__ W2) {
    int idx = blockIdx.x * 256 + threadIdx.x;       // n*512 + k
    int n = idx >> 9, k = idx & 511;
    g_w2h[idx] = __float2half_rn(W2[k * NH + n]);
}

// ============================================================================
// Fixup: out = part0 + part1 + b3, diag = -20
// ============================================================================
__global__ void k_fixup(const float* __restrict__ b3, float* __restrict__ out) {
    int idx = blockIdx.x * 256 + threadIdx.x;
    int i = idx >> 9, j = idx & 511;
    float v = g_part[idx] + g_part[NB * NB + idx] + b3[0];
    out[idx] = (i == j) ? -20.0f : v;
}

// ============================================================================
// Main fused kernel.
// grid = (4 j-blocks, 512 i, 2 n-chunks). CTA: M=128(j) x N=256(n) x K=512.
// K chunked by 64, double-buffered. A = tanh(yi[i]+yj[j]) computed in-kernel
// to fp16 smem; B = W2h streamed via cp.async. 8 warps, 64x64 warp tiles.
// ============================================================================
static constexpr int OFF_C1  = 0;        // 512 f32
static constexpr int OFF_B2  = 2048;     // 256 f32
static constexpr int OFF_W3  = 3072;     // 256 f32
static constexpr int OFF_RED = 4096;     // 512 f32 (4 n-warps x 128 rows)
static constexpr int OFF_A   = 8192;     // 2 x 128 rows x 128B = 32 KB
static constexpr int OFF_Bt  = 40960;    // 2 x 256 rows x 128B = 64 KB
static constexpr int SMEM_TOTAL = 106496;

__global__ void __launch_bounds__(256, 1)
pairwise_main(const float* __restrict__ b2g, const float* __restrict__ w3g) {
    extern __shared__ __align__(1024) char smem[];
    const uint32_t sb = smem_u32(smem);
    const int tid  = threadIdx.x;
    const int lane = tid & 31;
    const int w    = tid >> 5;
    const int mw   = w >> 2;          // 0..1  (m 64-row half)
    const int nw   = w & 3;           // 0..3  (n 64-col quarter)
    const int i    = blockIdx.y;
    const int j0   = blockIdx.x * 128;
    const int nb0  = blockIdx.z * 256;

    float* c1  = (float*)(smem + OFF_C1);
    float* b2s = (float*)(smem + OFF_B2);
    float* w3s = (float*)(smem + OFF_W3);
    float* red = (float*)(smem + OFF_RED);

    for (int k = tid; k < NH; k += 256) c1[k] = g_yi[i * NH + k];
    b2s[tid] = b2g[nb0 + tid];
    w3s[tid] = w3g[nb0 + tid];
    __syncthreads();

    // ---- stage helpers ----
    auto load_B = [&](int c, int buf) {
        const uint32_t base = sb + OFF_Bt + (uint32_t)buf * 32768u;
        const int k0 = c * 64;
#pragma unroll
        for (int t = 0; t < 8; t++) {
            int idx = tid + t * 256;         // 2048 16B units
            int n = idx >> 3, q = idx & 7;
            uint32_t byte = (uint32_t)(n * 128 + q * 16);
            uint32_t dst = base + SWZ(byte);
            const __half* src = g_w2h + (size_t)(nb0 + n) * NH + k0 + q * 8;
            CP_ASYNC16(dst, src);
        }
        CP_COMMIT();
    };

    auto compute_A = [&](int c, int buf) {
        const int k0 = c * 64;
        char* base = smem + OFF_A + buf * 16384;
#pragma unroll
        for (int t = 0; t < 4; t++) {
            int idx = tid + t * 256;         // 1024 16B units
            int row = idx >> 3, q = idx & 7;
            const float* yjp = g_yj + (size_t)(j0 + row) * NH + k0 + q * 8;
            float4 v0 = *(const float4*)(yjp);
            float4 v1 = *(const float4*)(yjp + 4);
            float4 a0 = *(const float4*)(c1 + k0 + q * 8);
            float4 a1 = *(const float4*)(c1 + k0 + q * 8 + 4);
            __half2 h0 = __floats2half2_rn(ftanh(v0.x + a0.x), ftanh(v0.y + a0.y));
            __half2 h1 = __floats2half2_rn(ftanh(v0.z + a0.z), ftanh(v0.w + a0.w));
            __half2 h2 = __floats2half2_rn(ftanh(v1.x + a1.x), ftanh(v1.y + a1.y));
            __half2 h3 = __floats2half2_rn(ftanh(v1.z + a1.z), ftanh(v1.w + a1.w));
            uint4 pk;
            pk.x = reinterpret_cast<uint32_t&>(h0);
            pk.y = reinterpret_cast<uint32_t&>(h1);
            pk.z = reinterpret_cast<uint32_t&>(h2);
            pk.w = reinterpret_cast<uint32_t&>(h3);
            uint32_t byte = (uint32_t)(row * 128 + q * 16);
            *(uint4*)(base + SWZ(byte)) = pk;
        }
    };

    // ---- accumulators + lane-constant ldmatrix addressing ----
    float acc[4][8][4];
#pragma unroll
    for (int a = 0; a < 4; a++)
#pragma unroll
        for (int b = 0; b < 8; b++)
#pragma unroll
            for (int c2 = 0; c2 < 4; c2++) acc[a][b][c2] = 0.0f;

    // A x4: m0=r0-7 kh0, m1=r8-15 kh0, m2=r0-7 kh1, m3=r8-15 kh1
    const uint32_t a_row = (uint32_t)(mw * 64 + ((lane >> 3) & 1) * 8 + (lane & 7));
    const uint32_t a_col = (uint32_t)(((lane >> 4) & 1) * 16);
    // B x4: m0=n0-7 kh0, m1=n0-7 kh1, m2=n8-15 kh0, m3=n8-15 kh1
    const uint32_t b_row = (uint32_t)(nw * 64 + ((lane >> 4) & 1) * 8 + (lane & 7));
    const uint32_t b_col = (uint32_t)(((lane >> 3) & 1) * 16);

    auto mma_chunk = [&](int buf) {
        const uint32_t Ab = sb + OFF_A  + (uint32_t)buf * 16384u;
        const uint32_t Bb = sb + OFF_Bt + (uint32_t)buf * 32768u;
#pragma unroll
        for (int kk = 0; kk < 4; kk++) {
            uint32_t afr[4][4], bfr[4][4];
#pragma unroll
            for (int mf = 0; mf < 4; mf++) {
                uint32_t byte = (a_row + mf * 16) * 128 + kk * 32 + a_col;
                uint32_t ad = Ab + SWZ(byte);
                LDSM4(afr[mf], ad);
            }
#pragma unroll
            for (int np = 0; np < 4; np++) {
                uint32_t byte = (b_row + np * 16) * 128 + kk * 32 + b_col;
                uint32_t bd = Bb + SWZ(byte);
                LDSM4(bfr[np], bd);
            }
#pragma unroll
            for (int mf = 0; mf < 4; mf++)
#pragma unroll
                for (int np = 0; np < 4; np++) {
                    MMA16816(acc[mf][2 * np],     afr[mf], bfr[np][0], bfr[np][1]);
                    MMA16816(acc[mf][2 * np + 1], afr[mf], bfr[np][2], bfr[np][3]);
                }
        }
    };

    // ---- pipeline: 8 K-chunks, double buffered ----
    load_B(0, 0);
    compute_A(0, 0);
    CP_WAIT0();
    __syncthreads();

#pragma unroll 1
    for (int c = 0; c < 8; c++) {
        const int buf = c & 1;
        if (c < 7) load_B(c + 1, buf ^ 1);
        mma_chunk(buf);
        if (c < 7) {
            compute_A(c + 1, buf ^ 1);
            CP_WAIT0();
        }
        __syncthreads();
    }

    // ---- epilogue: z = tanh(u + b2), partial = z . W3 over this n-chunk ----
    float part[8];
#pragma unroll
    for (int x = 0; x < 8; x++) part[x] = 0.0f;

#pragma unroll
    for (int mf = 0; mf < 4; mf++)
#pragma unroll
        for (int nf = 0; nf < 8; nf++)
#pragma unroll
            for (int c2 = 0; c2 < 4; c2++) {
                int n = nw * 64 + nf * 8 + ((lane & 3) << 1) + (c2 & 1);
                float u = acc[mf][nf][c2] + b2s[n];
                part[mf * 2 + (c2 >> 1)] = fmaf(ftanh(u), w3s[n], part[mf * 2 + (c2 >> 1)]);
            }

#pragma unroll
    for (int x = 0; x < 8; x++) {
        part[x] += __shfl_xor_sync(0xffffffffu, part[x], 1);
        part[x] += __shfl_xor_sync(0xffffffffu, part[x], 2);
    }
    if ((lane & 3) == 0) {
#pragma unroll
        for (int mf = 0; mf < 4; mf++)
#pragma unroll
            for (int hh = 0; hh < 2; hh++) {
                int m = mw * 64 + mf * 16 + hh * 8 + (lane >> 2);
                red[nw * 128 + m] = part[mf * 2 + hh];
            }
    }
    __syncthreads();

    if (tid < 128) {
        float s = red[tid] + red[128 + tid] + red[256 + tid] + red[384 + tid];
        g_part[(size_t)blockIdx.z * (NB * NB) + (size_t)i * NB + j0 + tid] = s;
    }
}

// ============================================================================
// kernel_launch
// ============================================================================
extern "C" void kernel_launch(void* const* d_in, const int* in_sizes, int n_in,
                              void* d_out, int out_size) {
    const float* h  = (const float*)d_in[0];
    const float* W1 = (const float*)d_in[1];
    const float* b1 = (const float*)d_in[2];
    const float* W2 = (const float*)d_in[3];
    const float* b2 = (const float*)d_in[4];
    const float* W3 = (const float*)d_in[5];
    const float* b3 = (const float*)d_in[6];
    float* out = (float*)d_out;

    k_gemm1<<<dim3(NH / 16, NB / 16, 2), dim3(16, 16)>>>(h, W1, b1);
    k_w2half<<<(NH * NH) / 256, 256>>>(W2);

    cudaFuncSetAttribute((const void*)pairwise_main,
                         cudaFuncAttributeMaxDynamicSharedMemorySize, SMEM_TOTAL);
    pairwise_main<<<dim3(4, NB, 2), 256, SMEM_TOTAL>>>(b2, W3);

    k_fixup<<<(NB * NB) / 256, 256>>>(b3, out);
}

// round 7
// speedup vs baseline: 1.1801x; 1.1801x over previous
#include <cuda_runtime.h>
#include <cuda_fp16.h>
#include <cstdint>

// ============================================================================
// B=512, D=256, H=512
//   yi = h@W1[:D]+b1 ; yj = h@W1[D:]
//   x = tanh(yi[i]+yj[j]); z = tanh(x@W2+b2); logits = z@W3+b3, diag=-20
// compute_103 PTX target (no 'a' suffix) -> tcgen05 unavailable; use baseline
// mma.sync.m16n8k16 + ldmatrix + cp.async.
// R7: 16 warps/CTA (was 8) for stall hiding; tanh.approx for A tile;
//     coalesced W2 transpose; trailing no-op so ncu slot hits main kernel.
// ============================================================================

#define NB 512
#define ND 256
#define NH 512

// -------------------- device scratch ----------------------------------------
__device__ __align__(16) float  g_yi[NB * NH];      // yi + b1 folded
__device__ __align__(16) float  g_yj[NB * NH];
__device__ __align__(16) __half g_w2h[NH * NH];     // W2h[n][k] = (half)W2[k][n]
__device__ __align__(16) float  g_part[2 * NB * NB];

// -------------------- helpers -----------------------------------------------
__device__ __forceinline__ uint32_t smem_u32(const void* p) {
    uint32_t a;
    asm("{ .reg .u64 t; cvta.to.shared.u64 t, %1; cvt.u32.u64 %0, t; }"
        : "=r"(a) : "l"(p));
    return a;
}

#define SWZ(o) ((o) ^ (((o) >> 3) & 0x70))

#define LDSM4(r, addr) \
    asm volatile("ldmatrix.sync.aligned.m8n8.x4.shared.b16 {%0,%1,%2,%3}, [%4];" \
                 : "=r"((r)[0]), "=r"((r)[1]), "=r"((r)[2]), "=r"((r)[3]) \
                 : "r"(addr))

#define MMA16816(d, a, b0, b1) \
    asm volatile("mma.sync.aligned.m16n8k16.row.col.f32.f16.f16.f32 " \
                 "{%0,%1,%2,%3}, {%4,%5,%6,%7}, {%8,%9}, {%0,%1,%2,%3};" \
                 : "+f"((d)[0]), "+f"((d)[1]), "+f"((d)[2]), "+f"((d)[3]) \
                 : "r"((a)[0]), "r"((a)[1]), "r"((a)[2]), "r"((a)[3]), \
                   "r"(b0), "r"(b1))

#define CP_ASYNC16(dst, src) \
    asm volatile("cp.async.cg.shared.global [%0], [%1], 16;" :: "r"(dst), "l"(src))
#define CP_COMMIT()  asm volatile("cp.async.commit_group;" ::: "memory")
#define CP_WAIT0()   asm volatile("cp.async.wait_group 0;" ::: "memory")

// Accurate tanh: (e^{2x}-1)/(e^{2x}+1), 2 MUFU (EX2 + RCP), few-ulp error.
__device__ __forceinline__ float ftanh(float x) {
    x = fminf(fmaxf(x, -15.0f), 15.0f);
    float e = __expf(2.0f * x);
    return __fdividef(e - 1.0f, e + 1.0f);
}

// Fast tanh: single MUFU (TANH). ~2^-11 abs error; used only for the A tile
// whose error is attenuated through W2 and W3 contractions.
__device__ __forceinline__ float ftanh_fast(float x) {
    float y;
    asm("tanh.approx.f32 %0, %1;" : "=f"(y) : "f"(x));
    return y;
}

// ============================================================================
// Stage A1: yi = h@W1[:D]+b1 (z=0), yj = h@W1[D:] (z=1)
// ============================================================================
__global__ void k_gemm1(const float* __restrict__ h, const float* __restrict__ W1,
                        const float* __restrict__ b1) {
    __shared__ float hs[16][16];
    __shared__ float ws[16][17];
    int tx = threadIdx.x, ty = threadIdx.y;
    int row = blockIdx.y * 16 + ty;   // i
    int col = blockIdx.x * 16 + tx;   // n
    int base = blockIdx.z * ND;
    float acc = (blockIdx.z == 0) ? b1[col] : 0.0f;
    for (int kt = 0; kt < ND; kt += 16) {
        hs[ty][tx] = h[row * ND + kt + tx];
        ws[ty][tx] = W1[(base + kt + ty) * NH + col];
        __syncthreads();
#pragma unroll
        for (int q = 0; q < 16; q++) acc = fmaf(hs[ty][q], ws[q][tx], acc);
        __syncthreads();
    }
    (blockIdx.z ? g_yj : g_yi)[row * NH + col] = acc;
}

// ============================================================================
// Stage A2: W2h[n][k] = half(W2[k][n]) — coalesced tiled transpose
// ============================================================================
__global__ void k_w2half(const float* __restrict__ W2) {
    __shared__ float t[32][33];
    int x = blockIdx.x * 32 + threadIdx.x;  // n (contiguous read)
    int y = blockIdx.y * 32 + threadIdx.y;  // k
    t[threadIdx.y][threadIdx.x] = W2[y * NH + x];
    __syncthreads();
    int xo = blockIdx.y * 32 + threadIdx.x; // k (contiguous write)
    int yo = blockIdx.x * 32 + threadIdx.y; // n
    g_w2h[yo * NH + xo] = __float2half_rn(t[threadIdx.x][threadIdx.y]);
}

// ============================================================================
// Fixup: out = part0 + part1 + b3, diag = -20
// ============================================================================
__global__ void k_fixup(const float* __restrict__ b3, float* __restrict__ out) {
    int idx = blockIdx.x * 256 + threadIdx.x;
    int i = idx >> 9, j = idx & 511;
    float v = g_part[idx] + g_part[NB * NB + idx] + b3[0];
    out[idx] = (i == j) ? -20.0f : v;
}

// No-op: shifts the ncu capture slot onto the main kernel next profile.
__global__ void k_nop() {}

// ============================================================================
// Main fused kernel.
// grid = (4 j-blocks, 512 i, 2 n-chunks). CTA: M=128(j) x N=256(n) x K=512.
// 512 threads / 16 warps; warp tile 32x64 (mw=w>>2 row group, nw=w&3 col
// group). K chunked by 64, double-buffered cp.async for B (W2h), A tile
// computed in-kernel (tanh.approx) to fp16 SW128 smem.
// ============================================================================
static constexpr int OFF_C1  = 0;        // 512 f32
static constexpr int OFF_B2  = 2048;     // 256 f32
static constexpr int OFF_W3  = 3072;     // 256 f32
static constexpr int OFF_RED = 4096;     // 512 f32 (4 n-warps x 128 rows)
static constexpr int OFF_A   = 8192;     // 2 x 128 rows x 128B = 32 KB
static constexpr int OFF_Bt  = 40960;    // 2 x 256 rows x 128B = 64 KB
static constexpr int SMEM_TOTAL = 106496;

__global__ void __launch_bounds__(512, 1)
pairwise_main(const float* __restrict__ b2g, const float* __restrict__ w3g) {
    extern __shared__ __align__(1024) char smem[];
    const uint32_t sb = smem_u32(smem);
    const int tid  = threadIdx.x;
    const int lane = tid & 31;
    const int w    = tid >> 5;
    const int mw   = w >> 2;          // 0..3  (32-row group)
    const int nw   = w & 3;           // 0..3  (64-col group)
    const int i    = blockIdx.y;
    const int j0   = blockIdx.x * 128;
    const int nb0  = blockIdx.z * 256;

    float* c1  = (float*)(smem + OFF_C1);
    float* b2s = (float*)(smem + OFF_B2);
    float* w3s = (float*)(smem + OFF_W3);
    float* red = (float*)(smem + OFF_RED);

    c1[tid & 511] = g_yi[i * NH + (tid & 511)];
    if (tid < 256) {
        b2s[tid] = b2g[nb0 + tid];
        w3s[tid] = w3g[nb0 + tid];
    }
    __syncthreads();

    // ---- stage helpers ----
    auto load_B = [&](int c, int buf) {
        const uint32_t base = sb + OFF_Bt + (uint32_t)buf * 32768u;
        const int k0 = c * 64;
#pragma unroll
        for (int t = 0; t < 4; t++) {
            int idx = tid + t * 512;         // 2048 16B units
            int n = idx >> 3, q = idx & 7;
            uint32_t byte = (uint32_t)(n * 128 + q * 16);
            uint32_t dst = base + SWZ(byte);
            const __half* src = g_w2h + (size_t)(nb0 + n) * NH + k0 + q * 8;
            CP_ASYNC16(dst, src);
        }
        CP_COMMIT();
    };

    auto compute_A = [&](int c, int buf) {
        const int k0 = c * 64;
        char* base = smem + OFF_A + buf * 16384;
#pragma unroll
        for (int t = 0; t < 2; t++) {
            int idx = tid + t * 512;         // 1024 16B units
            int row = idx >> 3, q = idx & 7;
            const float* yjp = g_yj + (size_t)(j0 + row) * NH + k0 + q * 8;
            float4 v0 = *(const float4*)(yjp);
            float4 v1 = *(const float4*)(yjp + 4);
            float4 a0 = *(const float4*)(c1 + k0 + q * 8);
            float4 a1 = *(const float4*)(c1 + k0 + q * 8 + 4);
            __half2 h0 = __floats2half2_rn(ftanh_fast(v0.x + a0.x), ftanh_fast(v0.y + a0.y));
            __half2 h1 = __floats2half2_rn(ftanh_fast(v0.z + a0.z), ftanh_fast(v0.w + a0.w));
            __half2 h2 = __floats2half2_rn(ftanh_fast(v1.x + a1.x), ftanh_fast(v1.y + a1.y));
            __half2 h3 = __floats2half2_rn(ftanh_fast(v1.z + a1.z), ftanh_fast(v1.w + a1.w));
            uint4 pk;
            pk.x = reinterpret_cast<uint32_t&>(h0);
            pk.y = reinterpret_cast<uint32_t&>(h1);
            pk.z = reinterpret_cast<uint32_t&>(h2);
            pk.w = reinterpret_cast<uint32_t&>(h3);
            uint32_t byte = (uint32_t)(row * 128 + q * 16);
            *(uint4*)(base + SWZ(byte)) = pk;
        }
    };

    // ---- accumulators + lane-constant ldmatrix addressing ----
    float acc[2][8][4];
#pragma unroll
    for (int a = 0; a < 2; a++)
#pragma unroll
        for (int b = 0; b < 8; b++)
#pragma unroll
            for (int c2 = 0; c2 < 4; c2++) acc[a][b][c2] = 0.0f;

    // A x4 fragment (m16k16): rows lane&15, k-half by lane>>4
    const uint32_t a_row = (uint32_t)(mw * 32 + (lane & 15));
    const uint32_t a_col = (uint32_t)(((lane >> 4) & 1) * 16);
    // B x4 fragment: m0=n0-7 kh0, m1=n0-7 kh1, m2=n8-15 kh0, m3=n8-15 kh1
    const uint32_t b_row = (uint32_t)(nw * 64 + ((lane >> 4) & 1) * 8 + (lane & 7));
    const uint32_t b_col = (uint32_t)(((lane >> 3) & 1) * 16);

    auto mma_chunk = [&](int buf) {
        const uint32_t Ab = sb + OFF_A  + (uint32_t)buf * 16384u;
        const uint32_t Bb = sb + OFF_Bt + (uint32_t)buf * 32768u;
#pragma unroll
        for (int kk = 0; kk < 4; kk++) {
            uint32_t afr[2][4], bfr[4][4];
#pragma unroll
            for (int mf = 0; mf < 2; mf++) {
                uint32_t byte = (a_row + mf * 16) * 128 + kk * 32 + a_col;
                LDSM4(afr[mf], Ab + SWZ(byte));
            }
#pragma unroll
            for (int np = 0; np < 4; np++) {
                uint32_t byte = (b_row + np * 16) * 128 + kk * 32 + b_col;
                LDSM4(bfr[np], Bb + SWZ(byte));
            }
#pragma unroll
            for (int mf = 0; mf < 2; mf++)
#pragma unroll
                for (int np = 0; np < 4; np++) {
                    MMA16816(acc[mf][2 * np],     afr[mf], bfr[np][0], bfr[np][1]);
                    MMA16816(acc[mf][2 * np + 1], afr[mf], bfr[np][2], bfr[np][3]);
                }
        }
    };

    // ---- pipeline: 8 K-chunks, double buffered ----
    load_B(0, 0);
    compute_A(0, 0);
    CP_WAIT0();
    __syncthreads();

#pragma unroll 1
    for (int c = 0; c < 8; c++) {
        const int buf = c & 1;
        if (c < 7) load_B(c + 1, buf ^ 1);
        mma_chunk(buf);
        if (c < 7) {
            compute_A(c + 1, buf ^ 1);
            CP_WAIT0();
        }
        __syncthreads();
    }

    // ---- epilogue: z = tanh(u + b2) [accurate], partial = z . W3 ----
    float part[4];
#pragma unroll
    for (int x = 0; x < 4; x++) part[x] = 0.0f;

#pragma unroll
    for (int mf = 0; mf < 2; mf++)
#pragma unroll
        for (int nf = 0; nf < 8; nf++)
#pragma unroll
            for (int c2 = 0; c2 < 4; c2++) {
                int n = nw * 64 + nf * 8 + ((lane & 3) << 1) + (c2 & 1);
                float u = acc[mf][nf][c2] + b2s[n];
                part[mf * 2 + (c2 >> 1)] = fmaf(ftanh(u), w3s[n], part[mf * 2 + (c2 >> 1)]);
            }

#pragma unroll
    for (int x = 0; x < 4; x++) {
        part[x] += __shfl_xor_sync(0xffffffffu, part[x], 1);
        part[x] += __shfl_xor_sync(0xffffffffu, part[x], 2);
    }
    if ((lane & 3) == 0) {
#pragma unroll
        for (int mf = 0; mf < 2; mf++)
#pragma unroll
            for (int hh = 0; hh < 2; hh++) {
                int m = mw * 32 + mf * 16 + hh * 8 + (lane >> 2);
                red[nw * 128 + m] = part[mf * 2 + hh];
            }
    }
    __syncthreads();

    if (tid < 128) {
        float s = red[tid] + red[128 + tid] + red[256 + tid] + red[384 + tid];
        g_part[(size_t)blockIdx.z * (NB * NB) + (size_t)i * NB + j0 + tid] = s;
    }
}

// ============================================================================
// kernel_launch
// ============================================================================
extern "C" void kernel_launch(void* const* d_in, const int* in_sizes, int n_in,
                              void* d_out, int out_size) {
    const float* h  = (const float*)d_in[0];
    const float* W1 = (const float*)d_in[1];
    const float* b1 = (const float*)d_in[2];
    const float* W2 = (const float*)d_in[3];
    const float* b2 = (const float*)d_in[4];
    const float* W3 = (const float*)d_in[5];
    const float* b3 = (const float*)d_in[6];
    float* out = (float*)d_out;

    k_gemm1<<<dim3(NH / 16, NB / 16, 2), dim3(16, 16)>>>(h, W1, b1);
    k_w2half<<<dim3(NH / 32, NH / 32), dim3(32, 32)>>>(W2);

    cudaFuncSetAttribute((const void*)pairwise_main,
                         cudaFuncAttributeMaxDynamicSharedMemorySize, SMEM_TOTAL);
    pairwise_main<<<dim3(4, NB, 2), 512, SMEM_TOTAL>>>(b2, W3);

    k_fixup<<<(NB * NB) / 256, 256>>>(b3, out);
    k_nop<<<1, 32>>>();   // shifts ncu capture slot onto pairwise_main
}

// round 8
// speedup vs baseline: 1.3175x; 1.1165x over previous
#include <cuda_runtime.h>
#include <cuda_fp16.h>
#include <cstdint>

// ============================================================================
// B=512, D=256, H=512
//   yi = h@W1[:D]+b1 ; yj = h@W1[D:]
//   x = tanh(yi[i]+yj[j]); z = tanh(x@W2+b2); logits = z@W3+b3, diag=-20
// compute_103 PTX target (no 'a') -> tcgen05 unavailable; baseline
// mma.sync.m16n8k16 + ldmatrix + cp.async.
// R8: interleave A-tile (MUFU) production inside the MMA loop so tensor and
//     MUFU pipes overlap; tanh.approx.f16x2 for A (1 MUFU / 2 elems);
//     tanh.approx.f32 epilogue.
// ============================================================================

#define NB 512
#define ND 256
#define NH 512

// -------------------- device scratch ----------------------------------------
__device__ __align__(16) float  g_yi[NB * NH];      // yi + b1 folded
__device__ __align__(16) float  g_yj[NB * NH];
__device__ __align__(16) __half g_w2h[NH * NH];     // W2h[n][k] = (half)W2[k][n]
__device__ __align__(16) float  g_part[2 * NB * NB];

// -------------------- helpers -----------------------------------------------
__device__ __forceinline__ uint32_t smem_u32(const void* p) {
    uint32_t a;
    asm("{ .reg .u64 t; cvta.to.shared.u64 t, %1; cvt.u32.u64 %0, t; }"
        : "=r"(a) : "l"(p));
    return a;
}

#define SWZ(o) ((o) ^ (((o) >> 3) & 0x70))

#define LDSM4(r, addr) \
    asm volatile("ldmatrix.sync.aligned.m8n8.x4.shared.b16 {%0,%1,%2,%3}, [%4];" \
                 : "=r"((r)[0]), "=r"((r)[1]), "=r"((r)[2]), "=r"((r)[3]) \
                 : "r"(addr))

#define MMA16816(d, a, b0, b1) \
    asm volatile("mma.sync.aligned.m16n8k16.row.col.f32.f16.f16.f32 " \
                 "{%0,%1,%2,%3}, {%4,%5,%6,%7}, {%8,%9}, {%0,%1,%2,%3};" \
                 : "+f"((d)[0]), "+f"((d)[1]), "+f"((d)[2]), "+f"((d)[3]) \
                 : "r"((a)[0]), "r"((a)[1]), "r"((a)[2]), "r"((a)[3]), \
                   "r"(b0), "r"(b1))

#define CP_ASYNC16(dst, src) \
    asm volatile("cp.async.cg.shared.global [%0], [%1], 16;" :: "r"(dst), "l"(src))
#define CP_COMMIT()  asm volatile("cp.async.commit_group;" ::: "memory")
#define CP_WAIT0()   asm volatile("cp.async.wait_group 0;" ::: "memory")

// Single-MUFU fp32 tanh approximation.
__device__ __forceinline__ float ftanh_fast(float x) {
    float y;
    asm("tanh.approx.f32 %0, %1;" : "=f"(y) : "f"(x));
    return y;
}

// Two tanhs in one MUFU: pack (lo,hi) fp32 -> half2, tanh.approx.f16x2.
__device__ __forceinline__ uint32_t htanh2(float lo, float hi) {
    __half2 p = __floats2half2_rn(lo, hi);
    uint32_t u = *reinterpret_cast<uint32_t*>(&p);
    uint32_t y;
    asm("tanh.approx.f16x2 %0, %1;" : "=r"(y) : "r"(u));
    return y;
}

// ============================================================================
// Stage A1: yi = h@W1[:D]+b1 (z=0), yj = h@W1[D:] (z=1)
// ============================================================================
__global__ void k_gemm1(const float* __restrict__ h, const float* __restrict__ W1,
                        const float* __restrict__ b1) {
    __shared__ float hs[16][16];
    __shared__ float ws[16][17];
    int tx = threadIdx.x, ty = threadIdx.y;
    int row = blockIdx.y * 16 + ty;   // i
    int col = blockIdx.x * 16 + tx;   // n
    int base = blockIdx.z * ND;
    float acc = (blockIdx.z == 0) ? b1[col] : 0.0f;
    for (int kt = 0; kt < ND; kt += 16) {
        hs[ty][tx] = h[row * ND + kt + tx];
        ws[ty][tx] = W1[(base + kt + ty) * NH + col];
        __syncthreads();
#pragma unroll
        for (int q = 0; q < 16; q++) acc = fmaf(hs[ty][q], ws[q][tx], acc);
        __syncthreads();
    }
    (blockIdx.z ? g_yj : g_yi)[row * NH + col] = acc;
}

// ============================================================================
// Stage A2: W2h[n][k] = half(W2[k][n]) — coalesced tiled transpose
// ============================================================================
__global__ void k_w2half(const float* __restrict__ W2) {
    __shared__ float t[32][33];
    int x = blockIdx.x * 32 + threadIdx.x;  // n
    int y = blockIdx.y * 32 + threadIdx.y;  // k
    t[threadIdx.y][threadIdx.x] = W2[y * NH + x];
    __syncthreads();
    int xo = blockIdx.y * 32 + threadIdx.x; // k
    int yo = blockIdx.x * 32 + threadIdx.y; // n
    g_w2h[yo * NH + xo] = __float2half_rn(t[threadIdx.x][threadIdx.y]);
}

// ============================================================================
// Fixup: out = part0 + part1 + b3, diag = -20
// ============================================================================
__global__ void k_fixup(const float* __restrict__ b3, float* __restrict__ out) {
    int idx = blockIdx.x * 256 + threadIdx.x;
    int i = idx >> 9, j = idx & 511;
    float v = g_part[idx] + g_part[NB * NB + idx] + b3[0];
    out[idx] = (i == j) ? -20.0f : v;
}

// ============================================================================
// Main fused kernel.
// grid = (4 j-blocks, 512 i, 2 n-chunks). CTA: M=128(j) x N=256(n) x K=512.
// 512 threads / 16 warps; warp tile 32x64. K chunked by 64, double-buffered.
// A tile for chunk c+1 is produced (LDG early, MUFU mid) INTERLEAVED with the
// MMA work of chunk c.
// ============================================================================
static constexpr int OFF_C1  = 0;        // 512 f32
static constexpr int OFF_B2  = 2048;     // 256 f32
static constexpr int OFF_W3  = 3072;     // 256 f32
static constexpr int OFF_RED = 4096;     // 512 f32
static constexpr int OFF_A   = 8192;     // 2 x 128 rows x 128B = 32 KB
static constexpr int OFF_Bt  = 40960;    // 2 x 256 rows x 128B = 64 KB
static constexpr int SMEM_TOTAL = 106496;

__global__ void __launch_bounds__(512, 1)
pairwise_main(const float* __restrict__ b2g, const float* __restrict__ w3g) {
    extern __shared__ __align__(1024) char smem[];
    const uint32_t sb = smem_u32(smem);
    const int tid  = threadIdx.x;
    const int lane = tid & 31;
    const int w    = tid >> 5;
    const int mw   = w >> 2;          // 0..3  (32-row group)
    const int nw   = w & 3;           // 0..3  (64-col group)
    const int i    = blockIdx.y;
    const int j0   = blockIdx.x * 128;
    const int nb0  = blockIdx.z * 256;

    float* c1  = (float*)(smem + OFF_C1);
    float* b2s = (float*)(smem + OFF_B2);
    float* w3s = (float*)(smem + OFF_W3);
    float* red = (float*)(smem + OFF_RED);

    c1[tid & 511] = g_yi[i * NH + (tid & 511)];
    if (tid < 256) {
        b2s[tid] = b2g[nb0 + tid];
        w3s[tid] = w3g[nb0 + tid];
    }
    __syncthreads();

    // per-thread A production coords: idx_t = tid + t*512 -> row, q
    const int a_r0 = tid >> 3;                  // t=0 row (0..63)
    const int a_r1 = (tid + 512) >> 3;          // t=1 row (64..127)
    const int a_q  = tid & 7;                   // 16B unit within row
    const float* yj_base0 = g_yj + (size_t)(j0 + a_r0) * NH + a_q * 8;
    const float* yj_base1 = g_yj + (size_t)(j0 + a_r1) * NH + a_q * 8;
    const uint32_t a_sw0 = SWZ((uint32_t)(a_r0 * 128 + a_q * 16));
    const uint32_t a_sw1 = SWZ((uint32_t)(a_r1 * 128 + a_q * 16));

    auto load_B = [&](int c, int buf) {
        const uint32_t base = sb + OFF_Bt + (uint32_t)buf * 32768u;
        const int k0 = c * 64;
#pragma unroll
        for (int t = 0; t < 4; t++) {
            int idx = tid + t * 512;
            int n = idx >> 3, q = idx & 7;
            uint32_t dst = base + SWZ((uint32_t)(n * 128 + q * 16));
            CP_ASYNC16(dst, g_w2h + (size_t)(nb0 + n) * NH + k0 + q * 8);
        }
        CP_COMMIT();
    };

    // A math from preloaded registers -> swizzled fp16 smem store
    auto a_math = [&](int c, int buf, const float4* v) {
        const int k0 = c * 64;
        char* base = smem + OFF_A + buf * 16384;
        float4 a0 = *(const float4*)(c1 + k0 + a_q * 8);
        float4 a1 = *(const float4*)(c1 + k0 + a_q * 8 + 4);
        uint4 pk0, pk1;
        pk0.x = htanh2(v[0].x + a0.x, v[0].y + a0.y);
        pk0.y = htanh2(v[0].z + a0.z, v[0].w + a0.w);
        pk0.z = htanh2(v[1].x + a1.x, v[1].y + a1.y);
        pk0.w = htanh2(v[1].z + a1.z, v[1].w + a1.w);
        pk1.x = htanh2(v[2].x + a0.x, v[2].y + a0.y);
        pk1.y = htanh2(v[2].z + a0.z, v[2].w + a0.w);
        pk1.z = htanh2(v[3].x + a1.x, v[3].y + a1.y);
        pk1.w = htanh2(v[3].z + a1.z, v[3].w + a1.w);
        *(uint4*)(base + a_sw0) = pk0;
        *(uint4*)(base + a_sw1) = pk1;
    };

    // ---- accumulators + lane-constant ldmatrix addressing ----
    float acc[2][8][4];
#pragma unroll
    for (int a = 0; a < 2; a++)
#pragma unroll
        for (int b = 0; b < 8; b++)
#pragma unroll
            for (int c2 = 0; c2 < 4; c2++) acc[a][b][c2] = 0.0f;

    const uint32_t a_row = (uint32_t)(mw * 32 + (lane & 15));
    const uint32_t a_col = (uint32_t)(((lane >> 4) & 1) * 16);
    const uint32_t b_row = (uint32_t)(nw * 64 + ((lane >> 4) & 1) * 8 + (lane & 7));
    const uint32_t b_col = (uint32_t)(((lane >> 3) & 1) * 16);

    auto mma_kk = [&](uint32_t Ab, uint32_t Bb, int kk) {
        uint32_t afr[2][4], bfr[4][4];
#pragma unroll
        for (int mf = 0; mf < 2; mf++) {
            uint32_t byte = (a_row + mf * 16) * 128 + kk * 32 + a_col;
            LDSM4(afr[mf], Ab + SWZ(byte));
        }
#pragma unroll
        for (int np = 0; np < 4; np++) {
            uint32_t byte = (b_row + np * 16) * 128 + kk * 32 + b_col;
            LDSM4(bfr[np], Bb + SWZ(byte));
        }
#pragma unroll
        for (int mf = 0; mf < 2; mf++)
#pragma unroll
            for (int np = 0; np < 4; np++) {
                MMA16816(acc[mf][2 * np],     afr[mf], bfr[np][0], bfr[np][1]);
                MMA16816(acc[mf][2 * np + 1], afr[mf], bfr[np][2], bfr[np][3]);
            }
    };

    // ---- prologue: chunk 0 ----
    load_B(0, 0);
    {
        float4 v[4];
        v[0] = *(const float4*)(yj_base0);
        v[1] = *(const float4*)(yj_base0 + 4);
        v[2] = *(const float4*)(yj_base1);
        v[3] = *(const float4*)(yj_base1 + 4);
        a_math(0, 0, v);
    }
    CP_WAIT0();
    __syncthreads();

    // ---- pipeline: 8 K-chunks, A production interleaved with MMA ----
#pragma unroll 1
    for (int c = 0; c < 8; c++) {
        const int buf = c & 1;
        const uint32_t Ab = sb + OFF_A  + (uint32_t)buf * 16384u;
        const uint32_t Bb = sb + OFF_Bt + (uint32_t)buf * 32768u;
        float4 v[4];
        if (c < 7) {
            load_B(c + 1, buf ^ 1);
            const int k1 = (c + 1) * 64;
            v[0] = *(const float4*)(yj_base0 + k1);
            v[1] = *(const float4*)(yj_base0 + k1 + 4);
            v[2] = *(const float4*)(yj_base1 + k1);
            v[3] = *(const float4*)(yj_base1 + k1 + 4);
        }
        mma_kk(Ab, Bb, 0);
        mma_kk(Ab, Bb, 1);
        if (c < 7) a_math(c + 1, buf ^ 1, v);
        mma_kk(Ab, Bb, 2);
        mma_kk(Ab, Bb, 3);
        if (c < 7) CP_WAIT0();
        __syncthreads();
    }

    // ---- epilogue: z = tanh.approx(u + b2), partial = z . W3 ----
    float part[4];
#pragma unroll
    for (int x = 0; x < 4; x++) part[x] = 0.0f;

#pragma unroll
    for (int mf = 0; mf < 2; mf++)
#pragma unroll
        for (int nf = 0; nf < 8; nf++)
#pragma unroll
            for (int c2 = 0; c2 < 4; c2++) {
                int n = nw * 64 + nf * 8 + ((lane & 3) << 1) + (c2 & 1);
                float u = acc[mf][nf][c2] + b2s[n];
                part[mf * 2 + (c2 >> 1)] = fmaf(ftanh_fast(u), w3s[n], part[mf * 2 + (c2 >> 1)]);
            }

#pragma unroll
    for (int x = 0; x < 4; x++) {
        part[x] += __shfl_xor_sync(0xffffffffu, part[x], 1);
        part[x] += __shfl_xor_sync(0xffffffffu, part[x], 2);
    }
    if ((lane & 3) == 0) {
#pragma unroll
        for (int mf = 0; mf < 2; mf++)
#pragma unroll
            for (int hh = 0; hh < 2; hh++) {
                int m = mw * 32 + mf * 16 + hh * 8 + (lane >> 2);
                red[nw * 128 + m] = part[mf * 2 + hh];
            }
    }
    __syncthreads();

    if (tid < 128) {
        float s = red[tid] + red[128 + tid] + red[256 + tid] + red[384 + tid];
        g_part[(size_t)blockIdx.z * (NB * NB) + (size_t)i * NB + j0 + tid] = s;
    }
}

// ============================================================================
// kernel_launch
// ============================================================================
extern "C" void kernel_launch(void* const* d_in, const int* in_sizes, int n_in,
                              void* d_out, int out_size) {
    const float* h  = (const float*)d_in[0];
    const float* W1 = (const float*)d_in[1];
    const float* b1 = (const float*)d_in[2];
    const float* W2 = (const float*)d_in[3];
    const float* b2 = (const float*)d_in[4];
    const float* W3 = (const float*)d_in[5];
    const float* b3 = (const float*)d_in[6];
    float* out = (float*)d_out;

    k_gemm1<<<dim3(NH / 16, NB / 16, 2), dim3(16, 16)>>>(h, W1, b1);
    k_w2half<<<dim3(NH / 32, NH / 32), dim3(32, 32)>>>(W2);

    cudaFuncSetAttribute((const void*)pairwise_main,
                         cudaFuncAttributeMaxDynamicSharedMemorySize, SMEM_TOTAL);
    pairwise_main<<<dim3(4, NB, 2), 512, SMEM_TOTAL>>>(b2, W3);

    k_fixup<<<(NB * NB) / 256, 256>>>(b3, out);
}

// round 10
// speedup vs baseline: 1.3874x; 1.0531x over previous
#include <cuda_runtime.h>
#include <cuda_fp16.h>
#include <cstdint>

// ============================================================================
// B=512, D=256, H=512
//   yi = h@W1[:D]+b1 ; yj = h@W1[D:]
//   x = tanh(yi[i]+yj[j]); z = tanh(x@W2+b2); logits = z@W3+b3, diag=-20
// compute_103 PTX target (no 'a') -> tcgen05 unavailable; baseline
// mma.sync.m16n8k16 + ldmatrix + cp.async.
// R9: one CTA handles the FULL N=512 via two passes over a resident K=512
//     A tile (computed once, 128KB smem) -> halves A-production work
//     chip-wide, kills the g_part round-trip and k_fixup launch.
// ============================================================================

#define NB 512
#define ND 256
#define NH 512

// -------------------- device scratch ----------------------------------------
__device__ __align__(16) float  g_yi[NB * NH];      // yi + b1 folded
__device__ __align__(16) float  g_yj[NB * NH];
__device__ __align__(16) __half g_w2h[NH * NH];     // W2h[n][k] = (half)W2[k][n]

// -------------------- helpers -----------------------------------------------
__device__ __forceinline__ uint32_t smem_u32(const void* p) {
    uint32_t a;
    asm("{ .reg .u64 t; cvta.to.shared.u64 t, %1; cvt.u32.u64 %0, t; }"
        : "=r"(a) : "l"(p));
    return a;
}

#define SWZ(o) ((o) ^ (((o) >> 3) & 0x70))

#define LDSM4(r, addr) \
    asm volatile("ldmatrix.sync.aligned.m8n8.x4.shared.b16 {%0,%1,%2,%3}, [%4];" \
                 : "=r"((r)[0]), "=r"((r)[1]), "=r"((r)[2]), "=r"((r)[3]) \
                 : "r"(addr))

#define MMA16816(d, a, b0, b1) \
    asm volatile("mma.sync.aligned.m16n8k16.row.col.f32.f16.f16.f32 " \
                 "{%0,%1,%2,%3}, {%4,%5,%6,%7}, {%8,%9}, {%0,%1,%2,%3};" \
                 : "+f"((d)[0]), "+f"((d)[1]), "+f"((d)[2]), "+f"((d)[3]) \
                 : "r"((a)[0]), "r"((a)[1]), "r"((a)[2]), "r"((a)[3]), \
                   "r"(b0), "r"(b1))

#define CP_ASYNC16(dst, src) \
    asm volatile("cp.async.cg.shared.global [%0], [%1], 16;" :: "r"(dst), "l"(src))
#define CP_COMMIT()  asm volatile("cp.async.commit_group;" ::: "memory")
#define CP_WAIT0()   asm volatile("cp.async.wait_group 0;" ::: "memory")

// Single-MUFU fp32 tanh approximation.
__device__ __forceinline__ float ftanh_fast(float x) {
    float y;
    asm("tanh.approx.f32 %0, %1;" : "=f"(y) : "f"(x));
    return y;
}

// Two tanhs in one MUFU: pack (lo,hi) fp32 -> half2, tanh.approx.f16x2.
__device__ __forceinline__ uint32_t htanh2(float lo, float hi) {
    __half2 p = __floats2half2_rn(lo, hi);
    uint32_t u = *reinterpret_cast<uint32_t*>(&p);
    uint32_t y;
    asm("tanh.approx.f16x2 %0, %1;" : "=r"(y) : "r"(u));
    return y;
}

// ============================================================================
// Stage A1: yi = h@W1[:D]+b1 (z=0), yj = h@W1[D:] (z=1)
// ============================================================================
__global__ void k_gemm1(const float* __restrict__ h, const float* __restrict__ W1,
                        const float* __restrict__ b1) {
    __shared__ float hs[16][16];
    __shared__ float ws[16][17];
    int tx = threadIdx.x, ty = threadIdx.y;
    int row = blockIdx.y * 16 + ty;   // i
    int col = blockIdx.x * 16 + tx;   // n
    int base = blockIdx.z * ND;
    float acc = (blockIdx.z == 0) ? b1[col] : 0.0f;
    for (int kt = 0; kt < ND; kt += 16) {
        hs[ty][tx] = h[row * ND + kt + tx];
        ws[ty][tx] = W1[(base + kt + ty) * NH + col];
        __syncthreads();
#pragma unroll
        for (int q = 0; q < 16; q++) acc = fmaf(hs[ty][q], ws[q][tx], acc);
        __syncthreads();
    }
    (blockIdx.z ? g_yj : g_yi)[row * NH + col] = acc;
}

// ============================================================================
// Stage A2: W2h[n][k] = half(W2[k][n]) — coalesced tiled transpose
// ============================================================================
__global__ void k_w2half(const float* __restrict__ W2) {
    __shared__ float t[32][33];
    int x = blockIdx.x * 32 + threadIdx.x;  // n
    int y = blockIdx.y * 32 + threadIdx.y;  // k
    t[threadIdx.y][threadIdx.x] = W2[y * NH + x];
    __syncthreads();
    int xo = blockIdx.y * 32 + threadIdx.x; // k
    int yo = blockIdx.x * 32 + threadIdx.y; // n
    g_w2h[yo * NH + xo] = __float2half_rn(t[threadIdx.x][threadIdx.y]);
}

// ============================================================================
// Main fused kernel.
// grid = (4 j-blocks, 512 i). CTA: M=128(j) x N=512(n, two passes) x K=512.
// 512 threads / 16 warps; warp tile 32x64. A tile (tanh(yi+yj), fp16 SW128)
// for ALL K=512 resident in smem, computed once during pass 0. B (W2h)
// streamed per 64-k chunk, double buffered, for each of the two n-halves.
// Logits written directly (diag=-20, +b3).
// ============================================================================
static constexpr int OFF_C1  = 0;        // 512 f32
static constexpr int OFF_B2  = 2048;     // 512 f32
static constexpr int OFF_W3  = 4096;     // 512 f32
static constexpr int OFF_RED = 6144;     // 512 f32
static constexpr int OFF_A   = 8192;     // 8 chunks x 128 rows x 128B = 128 KB
static constexpr int OFF_Bt  = 139264;   // 2 x 256 rows x 128B = 64 KB
static constexpr int SMEM_TOTAL = 204800;

__global__ void __launch_bounds__(512, 1)
pairwise_main(const float* __restrict__ b2g, const float* __restrict__ w3g,
              const float* __restrict__ b3g, float* __restrict__ out) {
    extern __shared__ __align__(1024) char smem[];
    const uint32_t sb = smem_u32(smem);
    const int tid  = threadIdx.x;
    const int lane = tid & 31;
    const int w    = tid >> 5;
    const int mw   = w >> 2;          // 0..3  (32-row group)
    const int nw   = w & 3;           // 0..3  (64-col group)
    const int i    = blockIdx.y;
    const int j0   = blockIdx.x * 128;

    float* c1  = (float*)(smem + OFF_C1);
    float* b2s = (float*)(smem + OFF_B2);
    float* w3s = (float*)(smem + OFF_W3);
    float* red = (float*)(smem + OFF_RED);

    c1[tid]  = g_yi[i * NH + tid];
    b2s[tid] = b2g[tid];
    w3s[tid] = w3g[tid];
    __syncthreads();

    // per-thread A production coords
    const int a_r0 = tid >> 3;                  // row (0..63)
    const int a_r1 = (tid + 512) >> 3;          // row (64..127)
    const int a_q  = tid & 7;                   // 16B unit within row
    const float* yj_base0 = g_yj + (size_t)(j0 + a_r0) * NH + a_q * 8;
    const float* yj_base1 = g_yj + (size_t)(j0 + a_r1) * NH + a_q * 8;
    const uint32_t a_sw0 = SWZ((uint32_t)(a_r0 * 128 + a_q * 16));
    const uint32_t a_sw1 = SWZ((uint32_t)(a_r1 * 128 + a_q * 16));

    auto load_B = [&](int nb0, int c, int buf) {
        const uint32_t base = sb + OFF_Bt + (uint32_t)buf * 32768u;
        const int k0 = c * 64;
#pragma unroll
        for (int t = 0; t < 4; t++) {
            int idx = tid + t * 512;
            int n = idx >> 3, q = idx & 7;
            uint32_t dst = base + SWZ((uint32_t)(n * 128 + q * 16));
            CP_ASYNC16(dst, g_w2h + (size_t)(nb0 + n) * NH + k0 + q * 8);
        }
        CP_COMMIT();
    };

    auto a_math = [&](int c, const float4* v) {
        const int k0 = c * 64;
        char* base = smem + OFF_A + c * 16384;
        float4 a0 = *(const float4*)(c1 + k0 + a_q * 8);
        float4 a1 = *(const float4*)(c1 + k0 + a_q * 8 + 4);
        uint4 pk0, pk1;
        pk0.x = htanh2(v[0].x + a0.x, v[0].y + a0.y);
        pk0.y = htanh2(v[0].z + a0.z, v[0].w + a0.w);
        pk0.z = htanh2(v[1].x + a1.x, v[1].y + a1.y);
        pk0.w = htanh2(v[1].z + a1.z, v[1].w + a1.w);
        pk1.x = htanh2(v[2].x + a0.x, v[2].y + a0.y);
        pk1.y = htanh2(v[2].z + a0.z, v[2].w + a0.w);
        pk1.z = htanh2(v[3].x + a1.x, v[3].y + a1.y);
        pk1.w = htanh2(v[3].z + a1.z, v[3].w + a1.w);
        *(uint4*)(base + a_sw0) = pk0;
        *(uint4*)(base + a_sw1) = pk1;
    };

    // ---- accumulators + lane-constant ldmatrix addressing ----
    float acc[2][8][4];
    float part[4];
#pragma unroll
    for (int x = 0; x < 4; x++) part[x] = 0.0f;

    const uint32_t a_row = (uint32_t)(mw * 32 + (lane & 15));
    const uint32_t a_col = (uint32_t)(((lane >> 4) & 1) * 16);
    const uint32_t b_row = (uint32_t)(nw * 64 + ((lane >> 4) & 1) * 8 + (lane & 7));
    const uint32_t b_col = (uint32_t)(((lane >> 3) & 1) * 16);

    auto acc_zero = [&]() {
#pragma unroll
        for (int a = 0; a < 2; a++)
#pragma unroll
            for (int b = 0; b < 8; b++)
#pragma unroll
                for (int c2 = 0; c2 < 4; c2++) acc[a][b][c2] = 0.0f;
    };

    auto mma_kk = [&](uint32_t Ab, uint32_t Bb, int kk) {
        uint32_t afr[2][4], bfr[4][4];
#pragma unroll
        for (int mf = 0; mf < 2; mf++) {
            uint32_t byte = (a_row + mf * 16) * 128 + kk * 32 + a_col;
            LDSM4(afr[mf], Ab + SWZ(byte));
        }
#pragma unroll
        for (int np = 0; np < 4; np++) {
            uint32_t byte = (b_row + np * 16) * 128 + kk * 32 + b_col;
            LDSM4(bfr[np], Bb + SWZ(byte));
        }
#pragma unroll
        for (int mf = 0; mf < 2; mf++)
#pragma unroll
            for (int np = 0; np < 4; np++) {
                MMA16816(acc[mf][2 * np],     afr[mf], bfr[np][0], bfr[np][1]);
                MMA16816(acc[mf][2 * np + 1], afr[mf], bfr[np][2], bfr[np][3]);
            }
    };

    // epilogue pass: z = tanh.approx(u + b2), part += z . W3 (n-half = nb0)
    auto epilogue = [&](int nb0) {
#pragma unroll
        for (int mf = 0; mf < 2; mf++)
#pragma unroll
            for (int nf = 0; nf < 8; nf++)
#pragma unroll
                for (int c2 = 0; c2 < 4; c2++) {
                    int n = nb0 + nw * 64 + nf * 8 + ((lane & 3) << 1) + (c2 & 1);
                    float u = acc[mf][nf][c2] + b2s[n];
                    part[mf * 2 + (c2 >> 1)] =
                        fmaf(ftanh_fast(u), w3s[n], part[mf * 2 + (c2 >> 1)]);
                }
    };

    // ======================= pass 0: n in [0,256) ==========================
    acc_zero();
    load_B(0, 0, 0);
    {
        float4 v[4];
        v[0] = *(const float4*)(yj_base0);
        v[1] = *(const float4*)(yj_base0 + 4);
        v[2] = *(const float4*)(yj_base1);
        v[3] = *(const float4*)(yj_base1 + 4);
        a_math(0, v);
    }
    CP_WAIT0();
    __syncthreads();

#pragma unroll 1
    for (int c = 0; c < 8; c++) {
        const int buf = c & 1;
        const uint32_t Ab = sb + OFF_A  + (uint32_t)c * 16384u;
        const uint32_t Bb = sb + OFF_Bt + (uint32_t)buf * 32768u;
        float4 v[4];
        if (c < 7) {
            load_B(0, c + 1, buf ^ 1);
            const int k1 = (c + 1) * 64;
            v[0] = *(const float4*)(yj_base0 + k1);
            v[1] = *(const float4*)(yj_base0 + k1 + 4);
            v[2] = *(const float4*)(yj_base1 + k1);
            v[3] = *(const float4*)(yj_base1 + k1 + 4);
        }
        mma_kk(Ab, Bb, 0);
        mma_kk(Ab, Bb, 1);
        if (c < 7) a_math(c + 1, v);
        mma_kk(Ab, Bb, 2);
        mma_kk(Ab, Bb, 3);
        if (c < 7) CP_WAIT0();
        __syncthreads();
    }

    // prefetch first B chunk of pass 1 while doing epilogue 0
    load_B(256, 0, 0);
    epilogue(0);
    CP_WAIT0();
    __syncthreads();

    // ======================= pass 1: n in [256,512) ========================
    acc_zero();
#pragma unroll 1
    for (int c = 0; c < 8; c++) {
        const int buf = c & 1;
        const uint32_t Ab = sb + OFF_A  + (uint32_t)c * 16384u;
        const uint32_t Bb = sb + OFF_Bt + (uint32_t)buf * 32768u;
        if (c < 7) load_B(256, c + 1, buf ^ 1);
        mma_kk(Ab, Bb, 0);
        mma_kk(Ab, Bb, 1);
        mma_kk(Ab, Bb, 2);
        mma_kk(Ab, Bb, 3);
        if (c < 7) CP_WAIT0();
        __syncthreads();
    }
    epilogue(256);

    // ======================= reduce + writeout =============================
#pragma unroll
    for (int x = 0; x < 4; x++) {
        part[x] += __shfl_xor_sync(0xffffffffu, part[x], 1);
        part[x] += __shfl_xor_sync(0xffffffffu, part[x], 2);
    }
    if ((lane & 3) == 0) {
#pragma unroll
        for (int mf = 0; mf < 2; mf++)
#pragma unroll
            for (int hh = 0; hh < 2; hh++) {
                int m = mw * 32 + mf * 16 + hh * 8 + (lane >> 2);
                red[nw * 128 + m] = part[mf * 2 + hh];
            }
    }
    __syncthreads();

    if (tid < 128) {
        float s = red[tid] + red[128 + tid] + red[256 + tid] + red[384 + tid]
                + b3g[0];
        int j = j0 + tid;
        out[(size_t)i * NB + j] = (j == i) ? -20.0f : s;
    }
}

// ============================================================================
// kernel_launch
// ============================================================================
extern "C" void kernel_launch(void* const* d_in, const int* in_sizes, int n_in,
                              void* d_out, int out_size) {
    const float* h  = (const float*)d_in[0];
    const float* W1 = (const float*)d_in[1];
    const float* b1 = (const float*)d_in[2];
    const float* W2 = (const float*)d_in[3];
    const float* b2 = (const float*)d_in[4];
    const float* W3 = (const float*)d_in[5];
    const float* b3 = (const float*)d_in[6];
    float* out = (float*)d_out;

    k_gemm1<<<dim3(NH / 16, NB / 16, 2), dim3(16, 16)>>>(h, W1, b1);
    k_w2half<<<dim3(NH / 32, NH / 32), dim3(32, 32)>>>(W2);

    cudaFuncSetAttribute((const void*)pairwise_main,
                         cudaFuncAttributeMaxDynamicSharedMemorySize, SMEM_TOTAL);
    pairwise_main<<<dim3(4, NB), 512, SMEM_TOTAL>>>(b2, W3, b3, out);
}

// round 12
// speedup vs baseline: 1.4442x; 1.0409x over previous
#include <cuda_runtime.h>
#include <cuda_fp16.h>
#include <cstdint>

// ============================================================================
// B=512, D=256, H=512
//   yi = h@W1[:D]+b1 ; yj = h@W1[D:]
//   x = tanh(yi[i]+yj[j]); z = tanh(x@W2+b2); logits = z@W3+b3, diag=-20
// compute_103 PTX target (no 'a') -> tcgen05 unavailable; baseline
// mma.sync.m16n8k16 + ldmatrix + cp.async.
// R11: k_gemm1 rewritten as register-tiled SGEMM (was 34us naive, measured);
//      main kernel unchanged from R9 (A-resident two-pass, ~73% of HMMA
//      issue floor by cycle model).
// ============================================================================

#define NB 512
#define ND 256
#define NH 512

// -------------------- device scratch ----------------------------------------
__device__ __align__(16) float  g_yi[NB * NH];      // yi + b1 folded
__device__ __align__(16) float  g_yj[NB * NH];
__device__ __align__(16) __half g_w2h[NH * NH];     // W2h[n][k] = (half)W2[k][n]

// -------------------- helpers -----------------------------------------------
__device__ __forceinline__ uint32_t smem_u32(const void* p) {
    uint32_t a;
    asm("{ .reg .u64 t; cvta.to.shared.u64 t, %1; cvt.u32.u64 %0, t; }"
        : "=r"(a) : "l"(p));
    return a;
}

#define SWZ(o) ((o) ^ (((o) >> 3) & 0x70))

#define LDSM4(r, addr) \
    asm volatile("ldmatrix.sync.aligned.m8n8.x4.shared.b16 {%0,%1,%2,%3}, [%4];" \
                 : "=r"((r)[0]), "=r"((r)[1]), "=r"((r)[2]), "=r"((r)[3]) \
                 : "r"(addr))

#define MMA16816(d, a, b0, b1) \
    asm volatile("mma.sync.aligned.m16n8k16.row.col.f32.f16.f16.f32 " \
                 "{%0,%1,%2,%3}, {%4,%5,%6,%7}, {%8,%9}, {%0,%1,%2,%3};" \
                 : "+f"((d)[0]), "+f"((d)[1]), "+f"((d)[2]), "+f"((d)[3]) \
                 : "r"((a)[0]), "r"((a)[1]), "r"((a)[2]), "r"((a)[3]), \
                   "r"(b0), "r"(b1))

#define CP_ASYNC16(dst, src) \
    asm volatile("cp.async.cg.shared.global [%0], [%1], 16;" :: "r"(dst), "l"(src))
#define CP_COMMIT()  asm volatile("cp.async.commit_group;" ::: "memory")
#define CP_WAIT0()   asm volatile("cp.async.wait_group 0;" ::: "memory")

// Single-MUFU fp32 tanh approximation.
__device__ __forceinline__ float ftanh_fast(float x) {
    float y;
    asm("tanh.approx.f32 %0, %1;" : "=f"(y) : "f"(x));
    return y;
}

// Two tanhs in one MUFU: pack (lo,hi) fp32 -> half2, tanh.approx.f16x2.
__device__ __forceinline__ uint32_t htanh2(float lo, float hi) {
    __half2 p = __floats2half2_rn(lo, hi);
    uint32_t u = *reinterpret_cast<uint32_t*>(&p);
    uint32_t y;
    asm("tanh.approx.f16x2 %0, %1;" : "=r"(y) : "r"(u));
    return y;
}

// ============================================================================
// Stage A1: yi = h@W1[:D]+b1 (z=0), yj = h@W1[D:] (z=1)
// Register-tiled SGEMM: 64x64 block tile, 256 threads, 4x4 per thread.
// ============================================================================
__global__ __launch_bounds__(256)
void k_gemm1(const float* __restrict__ h, const float* __restrict__ W1,
             const float* __restrict__ b1) {
    __shared__ float As[16][68];   // [k][row], padded (272B row stride, 16B-aligned)
    __shared__ float Bs[16][64];   // [k][col]
    const int t    = threadIdx.x;
    const int tx   = t & 15;       // col group
    const int ty   = t >> 4;       // row group
    const int row0 = blockIdx.y * 64;
    const int col0 = blockIdx.x * 64;
    const int base = blockIdx.z * ND;

    // A-load coords: 64 rows x 16 k, one float4 per thread
    const int lr = t >> 2;         // 0..63 row
    const int lq = t & 3;          // k float4 index
    // B-load coords: 16 k x 64 cols, one float4 per thread
    const int lk = t >> 4;         // 0..15 k
    const int lc = (t & 15) * 4;   // col

    float acc[4][4];
#pragma unroll
    for (int a = 0; a < 4; a++) {
#pragma unroll
        for (int b = 0; b < 4; b++)
            acc[a][b] = (blockIdx.z == 0) ? b1[col0 + tx * 4 + b] : 0.0f;
        if (blockIdx.z == 0 && a > 0) {
#pragma unroll
            for (int b = 0; b < 4; b++) acc[a][b] = acc[0][b];
        }
    }

    for (int kt = 0; kt < ND; kt += 16) {
        float4 av = *(const float4*)(h + (size_t)(row0 + lr) * ND + kt + lq * 4);
        As[lq * 4 + 0][lr] = av.x;
        As[lq * 4 + 1][lr] = av.y;
        As[lq * 4 + 2][lr] = av.z;
        As[lq * 4 + 3][lr] = av.w;
        *(float4*)&Bs[lk][lc] =
            *(const float4*)(W1 + (size_t)(base + kt + lk) * NH + col0 + lc);
        __syncthreads();
#pragma unroll
        for (int k = 0; k < 16; k++) {
            float4 ra = *(const float4*)&As[k][ty * 4];
            float4 rb = *(const float4*)&Bs[k][tx * 4];
            float A[4] = {ra.x, ra.y, ra.z, ra.w};
            float Bv[4] = {rb.x, rb.y, rb.z, rb.w};
#pragma unroll
            for (int a = 0; a < 4; a++)
#pragma unroll
                for (int b = 0; b < 4; b++)
                    acc[a][b] = fmaf(A[a], Bv[b], acc[a][b]);
        }
        __syncthreads();
    }

    float* dst = (blockIdx.z ? g_yj : g_yi);
#pragma unroll
    for (int a = 0; a < 4; a++) {
        float4 v = {acc[a][0], acc[a][1], acc[a][2], acc[a][3]};
        *(float4*)(dst + (size_t)(row0 + ty * 4 + a) * NH + col0 + tx * 4) = v;
    }
}

// ============================================================================
// Stage A2: W2h[n][k] = half(W2[k][n]) — coalesced tiled transpose
// ============================================================================
__global__ void k_w2half(const float* __restrict__ W2) {
    __shared__ float t[32][33];
    int x = blockIdx.x * 32 + threadIdx.x;  // n
    int y = blockIdx.y * 32 + threadIdx.y;  // k
    t[threadIdx.y][threadIdx.x] = W2[y * NH + x];
    __syncthreads();
    int xo = blockIdx.y * 32 + threadIdx.x; // k
    int yo = blockIdx.x * 32 + threadIdx.y; // n
    g_w2h[yo * NH + xo] = __float2half_rn(t[threadIdx.x][threadIdx.y]);
}

// ============================================================================
// Main fused kernel (unchanged from R9).
// grid = (4 j-blocks, 512 i). CTA: M=128(j) x N=512(n, two passes) x K=512.
// 512 threads / 16 warps; warp tile 32x64. A tile (tanh(yi+yj), fp16 SW128)
// for ALL K=512 resident in smem, computed once during pass 0. B (W2h)
// streamed per 64-k chunk, double buffered, per n-half.
// ============================================================================
static constexpr int OFF_C1  = 0;        // 512 f32
static constexpr int OFF_B2  = 2048;     // 512 f32
static constexpr int OFF_W3  = 4096;     // 512 f32
static constexpr int OFF_RED = 6144;     // 512 f32
static constexpr int OFF_A   = 8192;     // 8 chunks x 128 rows x 128B = 128 KB
static constexpr int OFF_Bt  = 139264;   // 2 x 256 rows x 128B = 64 KB
static constexpr int SMEM_TOTAL = 204800;

__global__ void __launch_bounds__(512, 1)
pairwise_main(const float* __restrict__ b2g, const float* __restrict__ w3g,
              const float* __restrict__ b3g, float* __restrict__ out) {
    extern __shared__ __align__(1024) char smem[];
    const uint32_t sb = smem_u32(smem);
    const int tid  = threadIdx.x;
    const int lane = tid & 31;
    const int w    = tid >> 5;
    const int mw   = w >> 2;          // 0..3  (32-row group)
    const int nw   = w & 3;           // 0..3  (64-col group)
    const int i    = blockIdx.y;
    const int j0   = blockIdx.x * 128;

    float* c1  = (float*)(smem + OFF_C1);
    float* b2s = (float*)(smem + OFF_B2);
    float* w3s = (float*)(smem + OFF_W3);
    float* red = (float*)(smem + OFF_RED);

    c1[tid]  = g_yi[i * NH + tid];
    b2s[tid] = b2g[tid];
    w3s[tid] = w3g[tid];
    __syncthreads();

    // per-thread A production coords
    const int a_r0 = tid >> 3;                  // row (0..63)
    const int a_r1 = (tid + 512) >> 3;          // row (64..127)
    const int a_q  = tid & 7;                   // 16B unit within row
    const float* yj_base0 = g_yj + (size_t)(j0 + a_r0) * NH + a_q * 8;
    const float* yj_base1 = g_yj + (size_t)(j0 + a_r1) * NH + a_q * 8;
    const uint32_t a_sw0 = SWZ((uint32_t)(a_r0 * 128 + a_q * 16));
    const uint32_t a_sw1 = SWZ((uint32_t)(a_r1 * 128 + a_q * 16));

    auto load_B = [&](int nb0, int c, int buf) {
        const uint32_t base = sb + OFF_Bt + (uint32_t)buf * 32768u;
        const int k0 = c * 64;
#pragma unroll
        for (int t = 0; t < 4; t++) {
            int idx = tid + t * 512;
            int n = idx >> 3, q = idx & 7;
            uint32_t dst = base + SWZ((uint32_t)(n * 128 + q * 16));
            CP_ASYNC16(dst, g_w2h + (size_t)(nb0 + n) * NH + k0 + q * 8);
        }
        CP_COMMIT();
    };

    auto a_math = [&](int c, const float4* v) {
        const int k0 = c * 64;
        char* base = smem + OFF_A + c * 16384;
        float4 a0 = *(const float4*)(c1 + k0 + a_q * 8);
        float4 a1 = *(const float4*)(c1 + k0 + a_q * 8 + 4);
        uint4 pk0, pk1;
        pk0.x = htanh2(v[0].x + a0.x, v[0].y + a0.y);
        pk0.y = htanh2(v[0].z + a0.z, v[0].w + a0.w);
        pk0.z = htanh2(v[1].x + a1.x, v[1].y + a1.y);
        pk0.w = htanh2(v[1].z + a1.z, v[1].w + a1.w);
        pk1.x = htanh2(v[2].x + a0.x, v[2].y + a0.y);
        pk1.y = htanh2(v[2].z + a0.z, v[2].w + a0.w);
        pk1.z = htanh2(v[3].x + a1.x, v[3].y + a1.y);
        pk1.w = htanh2(v[3].z + a1.z, v[3].w + a1.w);
        *(uint4*)(base + a_sw0) = pk0;
        *(uint4*)(base + a_sw1) = pk1;
    };

    // ---- accumulators + lane-constant ldmatrix addressing ----
    float acc[2][8][4];
    float part[4];
#pragma unroll
    for (int x = 0; x < 4; x++) part[x] = 0.0f;

    const uint32_t a_row = (uint32_t)(mw * 32 + (lane & 15));
    const uint32_t a_col = (uint32_t)(((lane >> 4) & 1) * 16);
    const uint32_t b_row = (uint32_t)(nw * 64 + ((lane >> 4) & 1) * 8 + (lane & 7));
    const uint32_t b_col = (uint32_t)(((lane >> 3) & 1) * 16);

    auto acc_zero = [&]() {
#pragma unroll
        for (int a = 0; a < 2; a++)
#pragma unroll
            for (int b = 0; b < 8; b++)
#pragma unroll
                for (int c2 = 0; c2 < 4; c2++) acc[a][b][c2] = 0.0f;
    };

    auto mma_kk = [&](uint32_t Ab, uint32_t Bb, int kk) {
        uint32_t afr[2][4], bfr[4][4];
#pragma unroll
        for (int mf = 0; mf < 2; mf++) {
            uint32_t byte = (a_row + mf * 16) * 128 + kk * 32 + a_col;
            LDSM4(afr[mf], Ab + SWZ(byte));
        }
#pragma unroll
        for (int np = 0; np < 4; np++) {
            uint32_t byte = (b_row + np * 16) * 128 + kk * 32 + b_col;
            LDSM4(bfr[np], Bb + SWZ(byte));
        }
#pragma unroll
        for (int mf = 0; mf < 2; mf++)
#pragma unroll
            for (int np = 0; np < 4; np++) {
                MMA16816(acc[mf][2 * np],     afr[mf], bfr[np][0], bfr[np][1]);
                MMA16816(acc[mf][2 * np + 1], afr[mf], bfr[np][2], bfr[np][3]);
            }
    };

    // epilogue pass: z = tanh.approx(u + b2), part += z . W3 (n-half = nb0)
    auto epilogue = [&](int nb0) {
#pragma unroll
        for (int mf = 0; mf < 2; mf++)
#pragma unroll
            for (int nf = 0; nf < 8; nf++)
#pragma unroll
                for (int c2 = 0; c2 < 4; c2++) {
                    int n = nb0 + nw * 64 + nf * 8 + ((lane & 3) << 1) + (c2 & 1);
                    float u = acc[mf][nf][c2] + b2s[n];
                    part[mf * 2 + (c2 >> 1)] =
                        fmaf(ftanh_fast(u), w3s[n], part[mf * 2 + (c2 >> 1)]);
                }
    };

    // ======================= pass 0: n in [0,256) ==========================
    acc_zero();
    load_B(0, 0, 0);
    {
        float4 v[4];
        v[0] = *(const float4*)(yj_base0);
        v[1] = *(const float4*)(yj_base0 + 4);
        v[2] = *(const float4*)(yj_base1);
        v[3] = *(const float4*)(yj_base1 + 4);
        a_math(0, v);
    }
    CP_WAIT0();
    __syncthreads();

#pragma unroll 1
    for (int c = 0; c < 8; c++) {
        const int buf = c & 1;
        const uint32_t Ab = sb + OFF_A  + (uint32_t)c * 16384u;
        const uint32_t Bb = sb + OFF_Bt + (uint32_t)buf * 32768u;
        float4 v[4];
        if (c < 7) {
            load_B(0, c + 1, buf ^ 1);
            const int k1 = (c + 1) * 64;
            v[0] = *(const float4*)(yj_base0 + k1);
            v[1] = *(const float4*)(yj_base0 + k1 + 4);
            v[2] = *(const float4*)(yj_base1 + k1);
            v[3] = *(const float4*)(yj_base1 + k1 + 4);
        }
        mma_kk(Ab, Bb, 0);
        mma_kk(Ab, Bb, 1);
        if (c < 7) a_math(c + 1, v);
        mma_kk(Ab, Bb, 2);
        mma_kk(Ab, Bb, 3);
        if (c < 7) CP_WAIT0();
        __syncthreads();
    }

    // prefetch first B chunk of pass 1 while doing epilogue 0
    load_B(256, 0, 0);
    epilogue(0);
    CP_WAIT0();
    __syncthreads();

    // ======================= pass 1: n in [256,512) ========================
    acc_zero();
#pragma unroll 1
    for (int c = 0; c < 8; c++) {
        const int buf = c & 1;
        const uint32_t Ab = sb + OFF_A  + (uint32_t)c * 16384u;
        const uint32_t Bb = sb + OFF_Bt + (uint32_t)buf * 32768u;
        if (c < 7) load_B(256, c + 1, buf ^ 1);
        mma_kk(Ab, Bb, 0);
        mma_kk(Ab, Bb, 1);
        mma_kk(Ab, Bb, 2);
        mma_kk(Ab, Bb, 3);
        if (c < 7) CP_WAIT0();
        __syncthreads();
    }
    epilogue(256);

    // ======================= reduce + writeout =============================
#pragma unroll
    for (int x = 0; x < 4; x++) {
        part[x] += __shfl_xor_sync(0xffffffffu, part[x], 1);
        part[x] += __shfl_xor_sync(0xffffffffu, part[x], 2);
    }
    if ((lane & 3) == 0) {
#pragma unroll
        for (int mf = 0; mf < 2; mf++)
#pragma unroll
            for (int hh = 0; hh < 2; hh++) {
                int m = mw * 32 + mf * 16 + hh * 8 + (lane >> 2);
                red[nw * 128 + m] = part[mf * 2 + hh];
            }
    }
    __syncthreads();

    if (tid < 128) {
        float s = red[tid] + red[128 + tid] + red[256 + tid] + red[384 + tid]
                + b3g[0];
        int j = j0 + tid;
        out[(size_t)i * NB + j] = (j == i) ? -20.0f : s;
    }
}

// ============================================================================
// kernel_launch
// ============================================================================
extern "C" void kernel_launch(void* const* d_in, const int* in_sizes, int n_in,
                              void* d_out, int out_size) {
    const float* h  = (const float*)d_in[0];
    const float* W1 = (const float*)d_in[1];
    const float* b1 = (const float*)d_in[2];
    const float* W2 = (const float*)d_in[3];
    const float* b2 = (const float*)d_in[4];
    const float* W3 = (const float*)d_in[5];
    const float* b3 = (const float*)d_in[6];
    float* out = (float*)d_out;

    k_gemm1<<<dim3(NH / 64, NB / 64, 2), 256>>>(h, W1, b1);
    k_w2half<<<dim3(NH / 32, NH / 32), dim3(32, 32)>>>(W2);

    cudaFuncSetAttribute((const void*)pairwise_main,
                         cudaFuncAttributeMaxDynamicSharedMemorySize, SMEM_TOTAL);
    pairwise_main<<<dim3(4, NB), 512, SMEM_TOTAL>>>(b2, W3, b3, out);
}

// round 13
// speedup vs baseline: 1.5336x; 1.0619x over previous
#include <cuda_runtime.h>
#include <cuda_fp16.h>
#include <cstdint>

// ============================================================================
// B=512, D=256, H=512
//   yi = h@W1[:D]+b1 ; yj = h@W1[D:]
//   x = tanh(yi[i]+yj[j]); z = tanh(x@W2+b2); logits = z@W3+b3, diag=-20
// compute_103 PTX target (no 'a') -> tcgen05 unavailable; baseline
// mma.sync.m16n8k16 + ldmatrix + cp.async.
// R13: k_gemm1 regridded to 256 CTAs (was 128, under one wave, measured
//      22.3us @ occ 12.7%); yi/yj stored fp16 -> A production uses
//      add.f16x2 + tanh.f16x2 and half the LDG bytes.
// ============================================================================

#define NB 512
#define ND 256
#define NH 512

// -------------------- device scratch ----------------------------------------
__device__ __align__(16) __half g_yih[NB * NH];     // yi + b1 folded, fp16
__device__ __align__(16) __half g_yjh[NB * NH];     // yj, fp16
__device__ __align__(16) __half g_w2h[NH * NH];     // W2h[n][k] = (half)W2[k][n]

// -------------------- helpers -----------------------------------------------
__device__ __forceinline__ uint32_t smem_u32(const void* p) {
    uint32_t a;
    asm("{ .reg .u64 t; cvta.to.shared.u64 t, %1; cvt.u32.u64 %0, t; }"
        : "=r"(a) : "l"(p));
    return a;
}

#define SWZ(o) ((o) ^ (((o) >> 3) & 0x70))

#define LDSM4(r, addr) \
    asm volatile("ldmatrix.sync.aligned.m8n8.x4.shared.b16 {%0,%1,%2,%3}, [%4];" \
                 : "=r"((r)[0]), "=r"((r)[1]), "=r"((r)[2]), "=r"((r)[3]) \
                 : "r"(addr))

#define MMA16816(d, a, b0, b1) \
    asm volatile("mma.sync.aligned.m16n8k16.row.col.f32.f16.f16.f32 " \
                 "{%0,%1,%2,%3}, {%4,%5,%6,%7}, {%8,%9}, {%0,%1,%2,%3};" \
                 : "+f"((d)[0]), "+f"((d)[1]), "+f"((d)[2]), "+f"((d)[3]) \
                 : "r"((a)[0]), "r"((a)[1]), "r"((a)[2]), "r"((a)[3]), \
                   "r"(b0), "r"(b1))

#define CP_ASYNC16(dst, src) \
    asm volatile("cp.async.cg.shared.global [%0], [%1], 16;" :: "r"(dst), "l"(src))
#define CP_COMMIT()  asm volatile("cp.async.commit_group;" ::: "memory")
#define CP_WAIT0()   asm volatile("cp.async.wait_group 0;" ::: "memory")

// Single-MUFU fp32 tanh approximation.
__device__ __forceinline__ float ftanh_fast(float x) {
    float y;
    asm("tanh.approx.f32 %0, %1;" : "=f"(y) : "f"(x));
    return y;
}

// tanh(a + b) on packed half2: one HADD2 + one MUFU for two elements.
__device__ __forceinline__ uint32_t htanh_add2(uint32_t a, uint32_t b) {
    uint32_t s, y;
    asm("add.rn.f16x2 %0, %1, %2;" : "=r"(s) : "r"(a), "r"(b));
    asm("tanh.approx.f16x2 %0, %1;" : "=r"(y) : "r"(s));
    return y;
}

// ============================================================================
// Stage A1: yi = h@W1[:D]+b1 (z=0), yj = h@W1[D:] (z=1), fp16 output.
// 32x64 tile, 128 threads, 4x4 per thread. grid (8,16,2) = 256 CTAs.
// ============================================================================
__global__ __launch_bounds__(128)
void k_gemm1(const float* __restrict__ h, const float* __restrict__ W1,
             const float* __restrict__ b1) {
    __shared__ float As[16][36];   // [k][row], padded
    __shared__ float Bs[16][64];   // [k][col]
    const int t    = threadIdx.x;
    const int tx   = t & 15;       // col group
    const int ty   = t >> 4;       // row group (0..7)
    const int row0 = blockIdx.y * 32;
    const int col0 = blockIdx.x * 64;
    const int base = blockIdx.z * ND;

    // A-load: 32 rows x 16 k = 128 float4, one per thread
    const int lr = t >> 2;         // 0..31 row
    const int lq = t & 3;          // k float4 index
    // B-load: 16 k x 64 cols = 256 float4, two per thread
    const int lk = t >> 4;         // 0..7 k
    const int lc = (t & 15) * 4;   // col

    float acc[4][4];
#pragma unroll
    for (int b = 0; b < 4; b++)
        acc[0][b] = (blockIdx.z == 0) ? b1[col0 + tx * 4 + b] : 0.0f;
#pragma unroll
    for (int a = 1; a < 4; a++)
#pragma unroll
        for (int b = 0; b < 4; b++) acc[a][b] = acc[0][b];

    for (int kt = 0; kt < ND; kt += 16) {
        float4 av = *(const float4*)(h + (size_t)(row0 + lr) * ND + kt + lq * 4);
        As[lq * 4 + 0][lr] = av.x;
        As[lq * 4 + 1][lr] = av.y;
        As[lq * 4 + 2][lr] = av.z;
        As[lq * 4 + 3][lr] = av.w;
        *(float4*)&Bs[lk][lc] =
            *(const float4*)(W1 + (size_t)(base + kt + lk) * NH + col0 + lc);
        *(float4*)&Bs[lk + 8][lc] =
            *(const float4*)(W1 + (size_t)(base + kt + lk + 8) * NH + col0 + lc);
        __syncthreads();
#pragma unroll
        for (int k = 0; k < 16; k++) {
            float4 ra = *(const float4*)&As[k][ty * 4];
            float4 rb = *(const float4*)&Bs[k][tx * 4];
            float A[4] = {ra.x, ra.y, ra.z, ra.w};
            float Bv[4] = {rb.x, rb.y, rb.z, rb.w};
#pragma unroll
            for (int a = 0; a < 4; a++)
#pragma unroll
                for (int b = 0; b < 4; b++)
                    acc[a][b] = fmaf(A[a], Bv[b], acc[a][b]);
        }
        __syncthreads();
    }

    __half* dst = (blockIdx.z ? g_yjh : g_yih);
#pragma unroll
    for (int a = 0; a < 4; a++) {
        __half2 lo = __floats2half2_rn(acc[a][0], acc[a][1]);
        __half2 hi = __floats2half2_rn(acc[a][2], acc[a][3]);
        __half2* p = (__half2*)(dst + (size_t)(row0 + ty * 4 + a) * NH + col0 + tx * 4);
        p[0] = lo;
        p[1] = hi;
    }
}

// ============================================================================
// Stage A2: W2h[n][k] = half(W2[k][n]) — coalesced tiled transpose
// ============================================================================
__global__ void k_w2half(const float* __restrict__ W2) {
    __shared__ float t[32][33];
    int x = blockIdx.x * 32 + threadIdx.x;  // n
    int y = blockIdx.y * 32 + threadIdx.y;  // k
    t[threadIdx.y][threadIdx.x] = W2[y * NH + x];
    __syncthreads();
    int xo = blockIdx.y * 32 + threadIdx.x; // k
    int yo = blockIdx.x * 32 + threadIdx.y; // n
    g_w2h[yo * NH + xo] = __float2half_rn(t[threadIdx.x][threadIdx.y]);
}

// ============================================================================
// Main fused kernel.
// grid = (4 j-blocks, 512 i). CTA: M=128(j) x N=512(n, two passes) x K=512.
// 512 threads / 16 warps; warp tile 32x64. A tile (tanh(yi+yj), fp16 SW128)
// for ALL K=512 resident in smem, computed once during pass 0 from fp16
// yi/yj (HADD2 + tanh.f16x2). B (W2h) streamed per 64-k chunk, double
// buffered, per n-half. Logits written directly (diag=-20, +b3).
// ============================================================================
static constexpr int OFF_C1  = 0;        // 512 half = 1KB
static constexpr int OFF_B2  = 2048;     // 512 f32
static constexpr int OFF_W3  = 4096;     // 512 f32
static constexpr int OFF_RED = 6144;     // 512 f32
static constexpr int OFF_A   = 8192;     // 8 chunks x 128 rows x 128B = 128 KB
static constexpr int OFF_Bt  = 139264;   // 2 x 256 rows x 128B = 64 KB
static constexpr int SMEM_TOTAL = 204800;

__global__ void __launch_bounds__(512, 1)
pairwise_main(const float* __restrict__ b2g, const float* __restrict__ w3g,
              const float* __restrict__ b3g, float* __restrict__ out) {
    extern __shared__ __align__(1024) char smem[];
    const uint32_t sb = smem_u32(smem);
    const int tid  = threadIdx.x;
    const int lane = tid & 31;
    const int w    = tid >> 5;
    const int mw   = w >> 2;          // 0..3  (32-row group)
    const int nw   = w & 3;           // 0..3  (64-col group)
    const int i    = blockIdx.y;
    const int j0   = blockIdx.x * 128;

    __half* c1h = (__half*)(smem + OFF_C1);
    float* b2s = (float*)(smem + OFF_B2);
    float* w3s = (float*)(smem + OFF_W3);
    float* red = (float*)(smem + OFF_RED);

    c1h[tid] = g_yih[i * NH + tid];
    b2s[tid] = b2g[tid];
    w3s[tid] = w3g[tid];
    __syncthreads();

    // per-thread A production coords: 2 rows x 8 halves (16B) each
    const int a_r0 = tid >> 3;                  // row (0..63)
    const int a_r1 = (tid + 512) >> 3;          // row (64..127)
    const int a_q  = tid & 7;                   // 16B unit within 128B row
    const __half* yjh0 = g_yjh + (size_t)(j0 + a_r0) * NH + a_q * 8;
    const __half* yjh1 = g_yjh + (size_t)(j0 + a_r1) * NH + a_q * 8;
    const uint32_t a_sw0 = SWZ((uint32_t)(a_r0 * 128 + a_q * 16));
    const uint32_t a_sw1 = SWZ((uint32_t)(a_r1 * 128 + a_q * 16));

    auto load_B = [&](int nb0, int c, int buf) {
        const uint32_t base = sb + OFF_Bt + (uint32_t)buf * 32768u;
        const int k0 = c * 64;
#pragma unroll
        for (int t = 0; t < 4; t++) {
            int idx = tid + t * 512;
            int n = idx >> 3, q = idx & 7;
            uint32_t dst = base + SWZ((uint32_t)(n * 128 + q * 16));
            CP_ASYNC16(dst, g_w2h + (size_t)(nb0 + n) * NH + k0 + q * 8);
        }
        CP_COMMIT();
    };

    // A math: v0/v1 = 8 yj halves per row; c = chunk index
    auto a_math = [&](int c, uint4 v0, uint4 v1) {
        const int k0 = c * 64;
        char* base = smem + OFF_A + c * 16384;
        const uint32_t* cc = (const uint32_t*)(c1h + k0 + a_q * 8);  // 4 half2
        uint32_t c0 = cc[0], c1v = cc[1], c2v = cc[2], c3v = cc[3];
        uint4 pk0, pk1;
        pk0.x = htanh_add2(v0.x, c0);
        pk0.y = htanh_add2(v0.y, c1v);
        pk0.z = htanh_add2(v0.z, c2v);
        pk0.w = htanh_add2(v0.w, c3v);
        pk1.x = htanh_add2(v1.x, c0);
        pk1.y = htanh_add2(v1.y, c1v);
        pk1.z = htanh_add2(v1.z, c2v);
        pk1.w = htanh_add2(v1.w, c3v);
        *(uint4*)(base + a_sw0) = pk0;
        *(uint4*)(base + a_sw1) = pk1;
    };

    // ---- accumulators + lane-constant ldmatrix addressing ----
    float acc[2][8][4];
    float part[4];
#pragma unroll
    for (int x = 0; x < 4; x++) part[x] = 0.0f;

    const uint32_t a_row = (uint32_t)(mw * 32 + (lane & 15));
    const uint32_t a_col = (uint32_t)(((lane >> 4) & 1) * 16);
    const uint32_t b_row = (uint32_t)(nw * 64 + ((lane >> 4) & 1) * 8 + (lane & 7));
    const uint32_t b_col = (uint32_t)(((lane >> 3) & 1) * 16);

    auto acc_zero = [&]() {
#pragma unroll
        for (int a = 0; a < 2; a++)
#pragma unroll
            for (int b = 0; b < 8; b++)
#pragma unroll
                for (int c2 = 0; c2 < 4; c2++) acc[a][b][c2] = 0.0f;
    };

    auto mma_kk = [&](uint32_t Ab, uint32_t Bb, int kk) {
        uint32_t afr[2][4], bfr[4][4];
#pragma unroll
        for (int mf = 0; mf < 2; mf++) {
            uint32_t byte = (a_row + mf * 16) * 128 + kk * 32 + a_col;
            LDSM4(afr[mf], Ab + SWZ(byte));
        }
#pragma unroll
        for (int np = 0; np < 4; np++) {
            uint32_t byte = (b_row + np * 16) * 128 + kk * 32 + b_col;
            LDSM4(bfr[np], Bb + SWZ(byte));
        }
#pragma unroll
        for (int mf = 0; mf < 2; mf++)
#pragma unroll
            for (int np = 0; np < 4; np++) {
                MMA16816(acc[mf][2 * np],     afr[mf], bfr[np][0], bfr[np][1]);
                MMA16816(acc[mf][2 * np + 1], afr[mf], bfr[np][2], bfr[np][3]);
            }
    };

    // epilogue pass: z = tanh.approx(u + b2), part += z . W3 (n-half = nb0)
    auto epilogue = [&](int nb0) {
#pragma unroll
        for (int mf = 0; mf < 2; mf++)
#pragma unroll
            for (int nf = 0; nf < 8; nf++)
#pragma unroll
                for (int c2 = 0; c2 < 4; c2++) {
                    int n = nb0 + nw * 64 + nf * 8 + ((lane & 3) << 1) + (c2 & 1);
                    float u = acc[mf][nf][c2] + b2s[n];
                    part[mf * 2 + (c2 >> 1)] =
                        fmaf(ftanh_fast(u), w3s[n], part[mf * 2 + (c2 >> 1)]);
                }
    };

    // ======================= pass 0: n in [0,256) ==========================
    acc_zero();
    load_B(0, 0, 0);
    a_math(0, *(const uint4*)(yjh0), *(const uint4*)(yjh1));
    CP_WAIT0();
    __syncthreads();

#pragma unroll 1
    for (int c = 0; c < 8; c++) {
        const int buf = c & 1;
        const uint32_t Ab = sb + OFF_A  + (uint32_t)c * 16384u;
        const uint32_t Bb = sb + OFF_Bt + (uint32_t)buf * 32768u;
        uint4 v0, v1;
        if (c < 7) {
            load_B(0, c + 1, buf ^ 1);
            const int k1 = (c + 1) * 64;
            v0 = *(const uint4*)(yjh0 + k1);
            v1 = *(const uint4*)(yjh1 + k1);
        }
        mma_kk(Ab, Bb, 0);
        mma_kk(Ab, Bb, 1);
        if (c < 7) a_math(c + 1, v0, v1);
        mma_kk(Ab, Bb, 2);
        mma_kk(Ab, Bb, 3);
        if (c < 7) CP_WAIT0();
        __syncthreads();
    }

    // prefetch first B chunk of pass 1 while doing epilogue 0
    load_B(256, 0, 0);
    epilogue(0);
    CP_WAIT0();
    __syncthreads();

    // ======================= pass 1: n in [256,512) ========================
    acc_zero();
#pragma unroll 1
    for (int c = 0; c < 8; c++) {
        const int buf = c & 1;
        const uint32_t Ab = sb + OFF_A  + (uint32_t)c * 16384u;
        const uint32_t Bb = sb + OFF_Bt + (uint32_t)buf * 32768u;
        if (c < 7) load_B(256, c + 1, buf ^ 1);
        mma_kk(Ab, Bb, 0);
        mma_kk(Ab, Bb, 1);
        mma_kk(Ab, Bb, 2);
        mma_kk(Ab, Bb, 3);
        if (c < 7) CP_WAIT0();
        __syncthreads();
    }
    epilogue(256);

    // ======================= reduce + writeout =============================
#pragma unroll
    for (int x = 0; x < 4; x++) {
        part[x] += __shfl_xor_sync(0xffffffffu, part[x], 1);
        part[x] += __shfl_xor_sync(0xffffffffu, part[x], 2);
    }
    if ((lane & 3) == 0) {
#pragma unroll
        for (int mf = 0; mf < 2; mf++)
#pragma unroll
            for (int hh = 0; hh < 2; hh++) {
                int m = mw * 32 + mf * 16 + hh * 8 + (lane >> 2);
                red[nw * 128 + m] = part[mf * 2 + hh];
            }
    }
    __syncthreads();

    if (tid < 128) {
        float s = red[tid] + red[128 + tid] + red[256 + tid] + red[384 + tid]
                + b3g[0];
        int j = j0 + tid;
        out[(size_t)i * NB + j] = (j == i) ? -20.0f : s;
    }
}

// ============================================================================
// kernel_launch
// ============================================================================
extern "C" void kernel_launch(void* const* d_in, const int* in_sizes, int n_in,
                              void* d_out, int out_size) {
    const float* h  = (const float*)d_in[0];
    const float* W1 = (const float*)d_in[1];
    const float* b1 = (const float*)d_in[2];
    const float* W2 = (const float*)d_in[3];
    const float* b2 = (const float*)d_in[4];
    const float* W3 = (const float*)d_in[5];
    const float* b3 = (const float*)d_in[6];
    float* out = (float*)d_out;

    k_gemm1<<<dim3(NH / 64, NB / 32, 2), 128>>>(h, W1, b1);
    k_w2half<<<dim3(NH / 32, NH / 32), dim3(32, 32)>>>(W2);

    cudaFuncSetAttribute((const void*)pairwise_main,
                         cudaFuncAttributeMaxDynamicSharedMemorySize, SMEM_TOTAL);
    pairwise_main<<<dim3(4, NB), 512, SMEM_TOTAL>>>(b2, W3, b3, out);
}

// round 15
// speedup vs baseline: 1.5373x; 1.0024x over previous
#include <cuda_runtime.h>
#include <cuda_fp16.h>
#include <cstdint>

// ============================================================================
// B=512, D=256, H=512
//   yi = h@W1[:D]+b1 ; yj = h@W1[D:]
//   x = tanh(yi[i]+yj[j]); z = tanh(x@W2+b2); logits = z@W3+b3, diag=-20
// compute_103 PTX target (no 'a') -> tcgen05 unavailable; baseline
// mma.sync.m16n8k16 + ldmatrix + cp.async.
// R14: k_gemm1 at 512 CTAs (32x32 tiles) for latency hiding (was 18.5us @
//      occ 11%); epilogue tanh via f16x2 (1 MUFU / 2 elems) to shrink the
//      phase-serial epilogue.
// ============================================================================

#define NB 512
#define ND 256
#define NH 512

// -------------------- device scratch ----------------------------------------
__device__ __align__(16) __half g_yih[NB * NH];     // yi + b1 folded, fp16
__device__ __align__(16) __half g_yjh[NB * NH];     // yj, fp16
__device__ __align__(16) __half g_w2h[NH * NH];     // W2h[n][k] = (half)W2[k][n]

// -------------------- helpers -----------------------------------------------
__device__ __forceinline__ uint32_t smem_u32(const void* p) {
    uint32_t a;
    asm("{ .reg .u64 t; cvta.to.shared.u64 t, %1; cvt.u32.u64 %0, t; }"
        : "=r"(a) : "l"(p));
    return a;
}

#define SWZ(o) ((o) ^ (((o) >> 3) & 0x70))

#define LDSM4(r, addr) \
    asm volatile("ldmatrix.sync.aligned.m8n8.x4.shared.b16 {%0,%1,%2,%3}, [%4];" \
                 : "=r"((r)[0]), "=r"((r)[1]), "=r"((r)[2]), "=r"((r)[3]) \
                 : "r"(addr))

#define MMA16816(d, a, b0, b1) \
    asm volatile("mma.sync.aligned.m16n8k16.row.col.f32.f16.f16.f32 " \
                 "{%0,%1,%2,%3}, {%4,%5,%6,%7}, {%8,%9}, {%0,%1,%2,%3};" \
                 : "+f"((d)[0]), "+f"((d)[1]), "+f"((d)[2]), "+f"((d)[3]) \
                 : "r"((a)[0]), "r"((a)[1]), "r"((a)[2]), "r"((a)[3]), \
                   "r"(b0), "r"(b1))

#define CP_ASYNC16(dst, src) \
    asm volatile("cp.async.cg.shared.global [%0], [%1], 16;" :: "r"(dst), "l"(src))
#define CP_COMMIT()  asm volatile("cp.async.commit_group;" ::: "memory")
#define CP_WAIT0()   asm volatile("cp.async.wait_group 0;" ::: "memory")

// tanh(a + b) on packed half2: one HADD2 + one MUFU for two elements.
__device__ __forceinline__ uint32_t htanh_add2(uint32_t a, uint32_t b) {
    uint32_t s, y;
    asm("add.rn.f16x2 %0, %1, %2;" : "=r"(s) : "r"(a), "r"(b));
    asm("tanh.approx.f16x2 %0, %1;" : "=r"(y) : "r"(s));
    return y;
}

// Two tanhs in one MUFU, fp32 in/out via half2.
__device__ __forceinline__ void tanh2f(float u0, float u1, float& z0, float& z1) {
    __half2 p = __floats2half2_rn(u0, u1);
    uint32_t u = *reinterpret_cast<uint32_t*>(&p);
    uint32_t r;
    asm("tanh.approx.f16x2 %0, %1;" : "=r"(r) : "r"(u));
    float2 f = __half22float2(*reinterpret_cast<__half2*>(&r));
    z0 = f.x;
    z1 = f.y;
}

// ============================================================================
// Stage A1: yi = h@W1[:D]+b1 (z=0), yj = h@W1[D:] (z=1), fp16 output.
// 32x32 tile, 128 threads, 2x4 per thread. grid (16,16,2) = 512 CTAs.
// ============================================================================
__global__ __launch_bounds__(128)
void k_gemm1(const float* __restrict__ h, const float* __restrict__ W1,
             const float* __restrict__ b1) {
    __shared__ float As[16][36];   // [k][row], padded
    __shared__ float Bs[16][36];   // [k][col], padded
    const int t    = threadIdx.x;
    const int tx   = t & 7;        // col group (x4)
    const int ty   = t >> 3;       // row group (x2), 0..15
    const int row0 = blockIdx.y * 32;
    const int col0 = blockIdx.x * 32;
    const int base = blockIdx.z * ND;

    // A-load: 32 rows x 16 k = 128 float4, one per thread
    const int lr = t >> 2;         // 0..31 row
    const int lq = t & 3;          // k float4 index
    // B-load: 16 k x 32 cols = 128 float4, one per thread
    const int lk = t >> 3;         // 0..15 k
    const int lc = (t & 7) * 4;    // col

    float acc[2][4];
#pragma unroll
    for (int b = 0; b < 4; b++)
        acc[0][b] = (blockIdx.z == 0) ? b1[col0 + tx * 4 + b] : 0.0f;
#pragma unroll
    for (int b = 0; b < 4; b++) acc[1][b] = acc[0][b];

    for (int kt = 0; kt < ND; kt += 16) {
        float4 av = *(const float4*)(h + (size_t)(row0 + lr) * ND + kt + lq * 4);
        As[lq * 4 + 0][lr] = av.x;
        As[lq * 4 + 1][lr] = av.y;
        As[lq * 4 + 2][lr] = av.z;
        As[lq * 4 + 3][lr] = av.w;
        *(float4*)&Bs[lk][lc] =
            *(const float4*)(W1 + (size_t)(base + kt + lk) * NH + col0 + lc);
        __syncthreads();
#pragma unroll
        for (int k = 0; k < 16; k++) {
            float a0 = As[k][ty * 2 + 0];
            float a1 = As[k][ty * 2 + 1];
            float4 rb = *(const float4*)&Bs[k][tx * 4];
            float Bv[4] = {rb.x, rb.y, rb.z, rb.w};
#pragma unroll
            for (int b = 0; b < 4; b++) {
                acc[0][b] = fmaf(a0, Bv[b], acc[0][b]);
                acc[1][b] = fmaf(a1, Bv[b], acc[1][b]);
            }
        }
        __syncthreads();
    }

    __half* dst = (blockIdx.z ? g_yjh : g_yih);
#pragma unroll
    for (int a = 0; a < 2; a++) {
        __half2 lo = __floats2half2_rn(acc[a][0], acc[a][1]);
        __half2 hi = __floats2half2_rn(acc[a][2], acc[a][3]);
        __half2* p = (__half2*)(dst + (size_t)(row0 + ty * 2 + a) * NH + col0 + tx * 4);
        p[0] = lo;
        p[1] = hi;
    }
}

// ============================================================================
// Stage A2: W2h[n][k] = half(W2[k][n]) — coalesced tiled transpose
// ============================================================================
__global__ void k_w2half(const float* __restrict__ W2) {
    __shared__ float t[32][33];
    int x = blockIdx.x * 32 + threadIdx.x;  // n
    int y = blockIdx.y * 32 + threadIdx.y;  // k
    t[threadIdx.y][threadIdx.x] = W2[y * NH + x];
    __syncthreads();
    int xo = blockIdx.y * 32 + threadIdx.x; // k
    int yo = blockIdx.x * 32 + threadIdx.y; // n
    g_w2h[yo * NH + xo] = __float2half_rn(t[threadIdx.x][threadIdx.y]);
}

// ============================================================================
// Main fused kernel.
// grid = (4 j-blocks, 512 i). CTA: M=128(j) x N=512(n, two passes) x K=512.
// 512 threads / 16 warps; warp tile 32x64. A tile (tanh(yi+yj), fp16 SW128)
// for ALL K=512 resident in smem, computed once during pass 0 from fp16
// yi/yj (HADD2 + tanh.f16x2). B (W2h) streamed per 64-k chunk, double
// buffered, per n-half. Epilogue tanh via f16x2 pairs.
// ============================================================================
static constexpr int OFF_C1  = 0;        // 512 half = 1KB
static constexpr int OFF_B2  = 2048;     // 512 f32
static constexpr int OFF_W3  = 4096;     // 512 f32
static constexpr int OFF_RED = 6144;     // 512 f32
static constexpr int OFF_A   = 8192;     // 8 chunks x 128 rows x 128B = 128 KB
static constexpr int OFF_Bt  = 139264;   // 2 x 256 rows x 128B = 64 KB
static constexpr int SMEM_TOTAL = 204800;

__global__ void __launch_bounds__(512, 1)
pairwise_main(const float* __restrict__ b2g, const float* __restrict__ w3g,
              const float* __restrict__ b3g, float* __restrict__ out) {
    extern __shared__ __align__(1024) char smem[];
    const uint32_t sb = smem_u32(smem);
    const int tid  = threadIdx.x;
    const int lane = tid & 31;
    const int w    = tid >> 5;
    const int mw   = w >> 2;          // 0..3  (32-row group)
    const int nw   = w & 3;           // 0..3  (64-col group)
    const int i    = blockIdx.y;
    const int j0   = blockIdx.x * 128;

    __half* c1h = (__half*)(smem + OFF_C1);
    float* b2s = (float*)(smem + OFF_B2);
    float* w3s = (float*)(smem + OFF_W3);
    float* red = (float*)(smem + OFF_RED);

    c1h[tid] = g_yih[i * NH + tid];
    b2s[tid] = b2g[tid];
    w3s[tid] = w3g[tid];
    __syncthreads();

    // per-thread A production coords: 2 rows x 8 halves (16B) each
    const int a_r0 = tid >> 3;                  // row (0..63)
    const int a_r1 = (tid + 512) >> 3;          // row (64..127)
    const int a_q  = tid & 7;                   // 16B unit within 128B row
    const __half* yjh0 = g_yjh + (size_t)(j0 + a_r0) * NH + a_q * 8;
    const __half* yjh1 = g_yjh + (size_t)(j0 + a_r1) * NH + a_q * 8;
    const uint32_t a_sw0 = SWZ((uint32_t)(a_r0 * 128 + a_q * 16));
    const uint32_t a_sw1 = SWZ((uint32_t)(a_r1 * 128 + a_q * 16));

    auto load_B = [&](int nb0, int c, int buf) {
        const uint32_t base = sb + OFF_Bt + (uint32_t)buf * 32768u;
        const int k0 = c * 64;
#pragma unroll
        for (int t = 0; t < 4; t++) {
            int idx = tid + t * 512;
            int n = idx >> 3, q = idx & 7;
            uint32_t dst = base + SWZ((uint32_t)(n * 128 + q * 16));
            CP_ASYNC16(dst, g_w2h + (size_t)(nb0 + n) * NH + k0 + q * 8);
        }
        CP_COMMIT();
    };

    // A math: v0/v1 = 8 yj halves per row; c = chunk index
    auto a_math = [&](int c, uint4 v0, uint4 v1) {
        const int k0 = c * 64;
        char* base = smem + OFF_A + c * 16384;
        const uint32_t* cc = (const uint32_t*)(c1h + k0 + a_q * 8);  // 4 half2
        uint32_t c0 = cc[0], c1v = cc[1], c2v = cc[2], c3v = cc[3];
        uint4 pk0, pk1;
        pk0.x = htanh_add2(v0.x, c0);
        pk0.y = htanh_add2(v0.y, c1v);
        pk0.z = htanh_add2(v0.z, c2v);
        pk0.w = htanh_add2(v0.w, c3v);
        pk1.x = htanh_add2(v1.x, c0);
        pk1.y = htanh_add2(v1.y, c1v);
        pk1.z = htanh_add2(v1.z, c2v);
        pk1.w = htanh_add2(v1.w, c3v);
        *(uint4*)(base + a_sw0) = pk0;
        *(uint4*)(base + a_sw1) = pk1;
    };

    // ---- accumulators + lane-constant ldmatrix addressing ----
    float acc[2][8][4];
    float part[4];
#pragma unroll
    for (int x = 0; x < 4; x++) part[x] = 0.0f;

    const uint32_t a_row = (uint32_t)(mw * 32 + (lane & 15));
    const uint32_t a_col = (uint32_t)(((lane >> 4) & 1) * 16);
    const uint32_t b_row = (uint32_t)(nw * 64 + ((lane >> 4) & 1) * 8 + (lane & 7));
    const uint32_t b_col = (uint32_t)(((lane >> 3) & 1) * 16);

    auto acc_zero = [&]() {
#pragma unroll
        for (int a = 0; a < 2; a++)
#pragma unroll
            for (int b = 0; b < 8; b++)
#pragma unroll
                for (int c2 = 0; c2 < 4; c2++) acc[a][b][c2] = 0.0f;
    };

    auto mma_kk = [&](uint32_t Ab, uint32_t Bb, int kk) {
        uint32_t afr[2][4], bfr[4][4];
#pragma unroll
        for (int mf = 0; mf < 2; mf++) {
            uint32_t byte = (a_row + mf * 16) * 128 + kk * 32 + a_col;
            LDSM4(afr[mf], Ab + SWZ(byte));
        }
#pragma unroll
        for (int np = 0; np < 4; np++) {
            uint32_t byte = (b_row + np * 16) * 128 + kk * 32 + b_col;
            LDSM4(bfr[np], Bb + SWZ(byte));
        }
#pragma unroll
        for (int mf = 0; mf < 2; mf++)
#pragma unroll
            for (int np = 0; np < 4; np++) {
                MMA16816(acc[mf][2 * np],     afr[mf], bfr[np][0], bfr[np][1]);
                MMA16816(acc[mf][2 * np + 1], afr[mf], bfr[np][2], bfr[np][3]);
            }
    };

    // epilogue pass: z = tanh(u + b2) via f16x2 pairs, part += z . W3
    auto epilogue = [&](int nb0) {
#pragma unroll
        for (int mf = 0; mf < 2; mf++)
#pragma unroll
            for (int nf = 0; nf < 8; nf++) {
                int n = nb0 + nw * 64 + nf * 8 + ((lane & 3) << 1);
                float w3a = w3s[n], w3b = w3s[n + 1];
                float b2a = b2s[n], b2b = b2s[n + 1];
                float z0, z1;
                tanh2f(acc[mf][nf][0] + b2a, acc[mf][nf][1] + b2b, z0, z1);
                part[mf * 2 + 0] = fmaf(z0, w3a, fmaf(z1, w3b, part[mf * 2 + 0]));
                tanh2f(acc[mf][nf][2] + b2a, acc[mf][nf][3] + b2b, z0, z1);
                part[mf * 2 + 1] = fmaf(z0, w3a, fmaf(z1, w3b, part[mf * 2 + 1]));
            }
    };

    // ======================= pass 0: n in [0,256) ==========================
    acc_zero();
    load_B(0, 0, 0);
    a_math(0, *(const uint4*)(yjh0), *(const uint4*)(yjh1));
    CP_WAIT0();
    __syncthreads();

#pragma unroll 1
    for (int c = 0; c < 8; c++) {
        const int buf = c & 1;
        const uint32_t Ab = sb + OFF_A  + (uint32_t)c * 16384u;
        const uint32_t Bb = sb + OFF_Bt + (uint32_t)buf * 32768u;
        uint4 v0, v1;
        if (c < 7) {
            load_B(0, c + 1, buf ^ 1);
            const int k1 = (c + 1) * 64;
            v0 = *(const uint4*)(yjh0 + k1);
            v1 = *(const uint4*)(yjh1 + k1);
        }
        mma_kk(Ab, Bb, 0);
        mma_kk(Ab, Bb, 1);
        if (c < 7) a_math(c + 1, v0, v1);
        mma_kk(Ab, Bb, 2);
        mma_kk(Ab, Bb, 3);
        if (c < 7) CP_WAIT0();
        __syncthreads();
    }

    // prefetch first B chunk of pass 1 while doing epilogue 0
    load_B(256, 0, 0);
    epilogue(0);
    CP_WAIT0();
    __syncthreads();

    // ======================= pass 1: n in [256,512) ========================
    acc_zero();
#pragma unroll 1
    for (int c = 0; c < 8; c++) {
        const int buf = c & 1;
        const uint32_t Ab = sb + OFF_A  + (uint32_t)c * 16384u;
        const uint32_t Bb = sb + OFF_Bt + (uint32_t)buf * 32768u;
        if (c < 7) load_B(256, c + 1, buf ^ 1);
        mma_kk(Ab, Bb, 0);
        mma_kk(Ab, Bb, 1);
        mma_kk(Ab, Bb, 2);
        mma_kk(Ab, Bb, 3);
        if (c < 7) CP_WAIT0();
        __syncthreads();
    }
    epilogue(256);

    // ======================= reduce + writeout =============================
#pragma unroll
    for (int x = 0; x < 4; x++) {
        part[x] += __shfl_xor_sync(0xffffffffu, part[x], 1);
        part[x] += __shfl_xor_sync(0xffffffffu, part[x], 2);
    }
    if ((lane & 3) == 0) {
#pragma unroll
        for (int mf = 0; mf < 2; mf++)
#pragma unroll
            for (int hh = 0; hh < 2; hh++) {
                int m = mw * 32 + mf * 16 + hh * 8 + (lane >> 2);
                red[nw * 128 + m] = part[mf * 2 + hh];
            }
    }
    __syncthreads();

    if (tid < 128) {
        float s = red[tid] + red[128 + tid] + red[256 + tid] + red[384 + tid]
                + b3g[0];
        int j = j0 + tid;
        out[(size_t)i * NB + j] = (j == i) ? -20.0f : s;
    }
}

// ============================================================================
// kernel_launch
// ============================================================================
extern "C" void kernel_launch(void* const* d_in, const int* in_sizes, int n_in,
                              void* d_out, int out_size) {
    const float* h  = (const float*)d_in[0];
    const float* W1 = (const float*)d_in[1];
    const float* b1 = (const float*)d_in[2];
    const float* W2 = (const float*)d_in[3];
    const float* b2 = (const float*)d_in[4];
    const float* W3 = (const float*)d_in[5];
    const float* b3 = (const float*)d_in[6];
    float* out = (float*)d_out;

    k_gemm1<<<dim3(NH / 32, NB / 32, 2), 128>>>(h, W1, b1);
    k_w2half<<<dim3(NH / 32, NH / 32), dim3(32, 32)>>>(W2);

    cudaFuncSetAttribute((const void*)pairwise_main,
                         cudaFuncAttributeMaxDynamicSharedMemorySize, SMEM_TOTAL);
    pairwise_main<<<dim3(4, NB), 512, SMEM_TOTAL>>>(b2, W3, b3, out);
}

// round 16
// speedup vs baseline: 1.6177x; 1.0523x over previous
#include <cuda_runtime.h>
#include <cuda_fp16.h>
#include <cstdint>

// ============================================================================
// B=512, D=256, H=512
//   yi = h@W1[:D]+b1 ; yj = h@W1[D:]
//   x = tanh(yi[i]+yj[j]); z = tanh(x@W2+b2); logits = z@W3+b3, diag=-20
// compute_103 PTX target (no 'a') -> tcgen05 unavailable; baseline
// mma.sync.m16n8k16 + ldmatrix + cp.async.
// R16: 8 warps x 64x64 warp tiles (3x less smem LDSM traffic per unit work,
//      neutral if HMMA-pipe-floor-bound); epilogue back to f32 tanh.approx
//      (R14 f16x2 pairing gained 0, cost accuracy); k_gemm1 = R13 config
//      (best measured, 18.5us).
// ============================================================================

#define NB 512
#define ND 256
#define NH 512

// -------------------- device scratch ----------------------------------------
__device__ __align__(16) __half g_yih[NB * NH];     // yi + b1 folded, fp16
__device__ __align__(16) __half g_yjh[NB * NH];     // yj, fp16
__device__ __align__(16) __half g_w2h[NH * NH];     // W2h[n][k] = (half)W2[k][n]

// -------------------- helpers -----------------------------------------------
__device__ __forceinline__ uint32_t smem_u32(const void* p) {
    uint32_t a;
    asm("{ .reg .u64 t; cvta.to.shared.u64 t, %1; cvt.u32.u64 %0, t; }"
        : "=r"(a) : "l"(p));
    return a;
}

#define SWZ(o) ((o) ^ (((o) >> 3) & 0x70))

#define LDSM4(r, addr) \
    asm volatile("ldmatrix.sync.aligned.m8n8.x4.shared.b16 {%0,%1,%2,%3}, [%4];" \
                 : "=r"((r)[0]), "=r"((r)[1]), "=r"((r)[2]), "=r"((r)[3]) \
                 : "r"(addr))

#define MMA16816(d, a, b0, b1) \
    asm volatile("mma.sync.aligned.m16n8k16.row.col.f32.f16.f16.f32 " \
                 "{%0,%1,%2,%3}, {%4,%5,%6,%7}, {%8,%9}, {%0,%1,%2,%3};" \
                 : "+f"((d)[0]), "+f"((d)[1]), "+f"((d)[2]), "+f"((d)[3]) \
                 : "r"((a)[0]), "r"((a)[1]), "r"((a)[2]), "r"((a)[3]), \
                   "r"(b0), "r"(b1))

#define CP_ASYNC16(dst, src) \
    asm volatile("cp.async.cg.shared.global [%0], [%1], 16;" :: "r"(dst), "l"(src))
#define CP_COMMIT()  asm volatile("cp.async.commit_group;" ::: "memory")
#define CP_WAIT0()   asm volatile("cp.async.wait_group 0;" ::: "memory")

// Single-MUFU fp32 tanh approximation (epilogue).
__device__ __forceinline__ float ftanh_fast(float x) {
    float y;
    asm("tanh.approx.f32 %0, %1;" : "=f"(y) : "f"(x));
    return y;
}

// tanh(a + b) on packed half2: one HADD2 + one MUFU for two elements (A tile).
__device__ __forceinline__ uint32_t htanh_add2(uint32_t a, uint32_t b) {
    uint32_t s, y;
    asm("add.rn.f16x2 %0, %1, %2;" : "=r"(s) : "r"(a), "r"(b));
    asm("tanh.approx.f16x2 %0, %1;" : "=r"(y) : "r"(s));
    return y;
}

// ============================================================================
// Stage A1: yi = h@W1[:D]+b1 (z=0), yj = h@W1[D:] (z=1), fp16 output.
// 32x64 tile, 128 threads, 4x4 per thread. grid (8,16,2) = 256 CTAs.
// (R13 configuration — best measured at 18.5us.)
// ============================================================================
__global__ __launch_bounds__(128)
void k_gemm1(const float* __restrict__ h, const float* __restrict__ W1,
             const float* __restrict__ b1) {
    __shared__ float As[16][36];   // [k][row], padded
    __shared__ float Bs[16][64];   // [k][col]
    const int t    = threadIdx.x;
    const int tx   = t & 15;       // col group
    const int ty   = t >> 4;       // row group (0..7)
    const int row0 = blockIdx.y * 32;
    const int col0 = blockIdx.x * 64;
    const int base = blockIdx.z * ND;

    const int lr = t >> 2;         // 0..31 row
    const int lq = t & 3;          // k float4 index
    const int lk = t >> 4;         // 0..7 k
    const int lc = (t & 15) * 4;   // col

    float acc[4][4];
#pragma unroll
    for (int b = 0; b < 4; b++)
        acc[0][b] = (blockIdx.z == 0) ? b1[col0 + tx * 4 + b] : 0.0f;
#pragma unroll
    for (int a = 1; a < 4; a++)
#pragma unroll
        for (int b = 0; b < 4; b++) acc[a][b] = acc[0][b];

    for (int kt = 0; kt < ND; kt += 16) {
        float4 av = *(const float4*)(h + (size_t)(row0 + lr) * ND + kt + lq * 4);
        As[lq * 4 + 0][lr] = av.x;
        As[lq * 4 + 1][lr] = av.y;
        As[lq * 4 + 2][lr] = av.z;
        As[lq * 4 + 3][lr] = av.w;
        *(float4*)&Bs[lk][lc] =
            *(const float4*)(W1 + (size_t)(base + kt + lk) * NH + col0 + lc);
        *(float4*)&Bs[lk + 8][lc] =
            *(const float4*)(W1 + (size_t)(base + kt + lk + 8) * NH + col0 + lc);
        __syncthreads();
#pragma unroll
        for (int k = 0; k < 16; k++) {
            float4 ra = *(const float4*)&As[k][ty * 4];
            float4 rb = *(const float4*)&Bs[k][tx * 4];
            float A[4] = {ra.x, ra.y, ra.z, ra.w};
            float Bv[4] = {rb.x, rb.y, rb.z, rb.w};
#pragma unroll
            for (int a = 0; a < 4; a++)
#pragma unroll
                for (int b = 0; b < 4; b++)
                    acc[a][b] = fmaf(A[a], Bv[b], acc[a][b]);
        }
        __syncthreads();
    }

    __half* dst = (blockIdx.z ? g_yjh : g_yih);
#pragma unroll
    for (int a = 0; a < 4; a++) {
        __half2 lo = __floats2half2_rn(acc[a][0], acc[a][1]);
        __half2 hi = __floats2half2_rn(acc[a][2], acc[a][3]);
        __half2* p = (__half2*)(dst + (size_t)(row0 + ty * 4 + a) * NH + col0 + tx * 4);
        p[0] = lo;
        p[1] = hi;
    }
}

// ============================================================================
// Stage A2: W2h[n][k] = half(W2[k][n]) — coalesced tiled transpose
// ============================================================================
__global__ void k_w2half(const float* __restrict__ W2) {
    __shared__ float t[32][33];
    int x = blockIdx.x * 32 + threadIdx.x;  // n
    int y = blockIdx.y * 32 + threadIdx.y;  // k
    t[threadIdx.y][threadIdx.x] = W2[y * NH + x];
    __syncthreads();
    int xo = blockIdx.y * 32 + threadIdx.x; // k
    int yo = blockIdx.x * 32 + threadIdx.y; // n
    g_w2h[yo * NH + xo] = __float2half_rn(t[threadIdx.x][threadIdx.y]);
}

// ============================================================================
// Main fused kernel.
// grid = (4 j-blocks, 512 i). CTA: M=128(j) x N=512(n, two passes) x K=512.
// 256 threads / 8 warps; warp tile 64x64 (mw=w&1 row half, nw=w>>1 col
// quarter). A tile (tanh(yi+yj), fp16 SW128) for ALL K=512 resident in smem,
// computed once during pass 0 from fp16 yi/yj. B (W2h) streamed per 64-k
// chunk, double buffered, per n-half. Logits written directly.
// ============================================================================
static constexpr int OFF_C1  = 0;        // 512 half = 1KB
static constexpr int OFF_B2  = 2048;     // 512 f32
static constexpr int OFF_W3  = 4096;     // 512 f32
static constexpr int OFF_RED = 6144;     // 512 f32
static constexpr int OFF_A   = 8192;     // 8 chunks x 128 rows x 128B = 128 KB
static constexpr int OFF_Bt  = 139264;   // 2 x 256 rows x 128B = 64 KB
static constexpr int SMEM_TOTAL = 204800;

__global__ void __launch_bounds__(256, 1)
pairwise_main(const float* __restrict__ b2g, const float* __restrict__ w3g,
              const float* __restrict__ b3g, float* __restrict__ out) {
    extern __shared__ __align__(1024) char smem[];
    const uint32_t sb = smem_u32(smem);
    const int tid  = threadIdx.x;
    const int lane = tid & 31;
    const int w    = tid >> 5;
    const int mw   = w & 1;           // 0..1  (64-row half)
    const int nw   = w >> 1;          // 0..3  (64-col quarter)
    const int i    = blockIdx.y;
    const int j0   = blockIdx.x * 128;

    __half* c1h = (__half*)(smem + OFF_C1);
    float* b2s = (float*)(smem + OFF_B2);
    float* w3s = (float*)(smem + OFF_W3);
    float* red = (float*)(smem + OFF_RED);

    for (int k = tid; k < NH; k += 256) {
        c1h[k] = g_yih[i * NH + k];
        b2s[k] = b2g[k];
        w3s[k] = w3g[k];
    }
    __syncthreads();

    // per-thread A production coords: 4 rows x 8 halves (16B) each
    const int a_q = tid & 7;                    // 16B unit within 128B row
    int a_r[4];
    const __half* yjp[4];
    uint32_t a_sw[4];
#pragma unroll
    for (int t = 0; t < 4; t++) {
        a_r[t] = (tid + t * 256) >> 3;          // rows 0..127
        yjp[t] = g_yjh + (size_t)(j0 + a_r[t]) * NH + a_q * 8;
        a_sw[t] = SWZ((uint32_t)(a_r[t] * 128 + a_q * 16));
    }

    auto load_B = [&](int nb0, int c, int buf) {
        const uint32_t base = sb + OFF_Bt + (uint32_t)buf * 32768u;
        const int k0 = c * 64;
#pragma unroll
        for (int t = 0; t < 8; t++) {
            int idx = tid + t * 256;
            int n = idx >> 3, q = idx & 7;
            uint32_t dst = base + SWZ((uint32_t)(n * 128 + q * 16));
            CP_ASYNC16(dst, g_w2h + (size_t)(nb0 + n) * NH + k0 + q * 8);
        }
        CP_COMMIT();
    };

    // A math: v[t] = 8 yj halves for row a_r[t]; c = chunk index
    auto a_math = [&](int c, const uint4* v) {
        const int k0 = c * 64;
        char* base = smem + OFF_A + c * 16384;
        const uint32_t* cc = (const uint32_t*)(c1h + k0 + a_q * 8);  // 4 half2
        uint32_t c0 = cc[0], c1v = cc[1], c2v = cc[2], c3v = cc[3];
#pragma unroll
        for (int t = 0; t < 4; t++) {
            uint4 pk;
            pk.x = htanh_add2(v[t].x, c0);
            pk.y = htanh_add2(v[t].y, c1v);
            pk.z = htanh_add2(v[t].z, c2v);
            pk.w = htanh_add2(v[t].w, c3v);
            *(uint4*)(base + a_sw[t]) = pk;
        }
    };

    // ---- accumulators + lane-constant ldmatrix addressing ----
    float acc[4][8][4];
    float part[8];
#pragma unroll
    for (int x = 0; x < 8; x++) part[x] = 0.0f;

    const uint32_t a_row = (uint32_t)(mw * 64 + (lane & 15));
    const uint32_t a_col = (uint32_t)(((lane >> 4) & 1) * 16);
    const uint32_t b_row = (uint32_t)(nw * 64 + ((lane >> 4) & 1) * 8 + (lane & 7));
    const uint32_t b_col = (uint32_t)(((lane >> 3) & 1) * 16);

    auto acc_zero = [&]() {
#pragma unroll
        for (int a = 0; a < 4; a++)
#pragma unroll
            for (int b = 0; b < 8; b++)
#pragma unroll
                for (int c2 = 0; c2 < 4; c2++) acc[a][b][c2] = 0.0f;
    };

    auto mma_kk = [&](uint32_t Ab, uint32_t Bb, int kk) {
        uint32_t afr[4][4], bfr[4][4];
#pragma unroll
        for (int mf = 0; mf < 4; mf++) {
            uint32_t byte = (a_row + mf * 16) * 128 + kk * 32 + a_col;
            LDSM4(afr[mf], Ab + SWZ(byte));
        }
#pragma unroll
        for (int np = 0; np < 4; np++) {
            uint32_t byte = (b_row + np * 16) * 128 + kk * 32 + b_col;
            LDSM4(bfr[np], Bb + SWZ(byte));
        }
#pragma unroll
        for (int mf = 0; mf < 4; mf++)
#pragma unroll
            for (int np = 0; np < 4; np++) {
                MMA16816(acc[mf][2 * np],     afr[mf], bfr[np][0], bfr[np][1]);
                MMA16816(acc[mf][2 * np + 1], afr[mf], bfr[np][2], bfr[np][3]);
            }
    };

    // epilogue pass: z = tanh.approx.f32(u + b2), part += z . W3 (n-half nb0)
    auto epilogue = [&](int nb0) {
#pragma unroll
        for (int mf = 0; mf < 4; mf++)
#pragma unroll
            for (int nf = 0; nf < 8; nf++)
#pragma unroll
                for (int c2 = 0; c2 < 4; c2++) {
                    int n = nb0 + nw * 64 + nf * 8 + ((lane & 3) << 1) + (c2 & 1);
                    float u = acc[mf][nf][c2] + b2s[n];
                    part[mf * 2 + (c2 >> 1)] =
                        fmaf(ftanh_fast(u), w3s[n], part[mf * 2 + (c2 >> 1)]);
                }
    };

    // ======================= pass 0: n in [0,256) ==========================
    acc_zero();
    load_B(0, 0, 0);
    {
        uint4 v[4];
#pragma unroll
        for (int t = 0; t < 4; t++) v[t] = *(const uint4*)(yjp[t]);
        a_math(0, v);
    }
    CP_WAIT0();
    __syncthreads();

#pragma unroll 1
    for (int c = 0; c < 8; c++) {
        const int buf = c & 1;
        const uint32_t Ab = sb + OFF_A  + (uint32_t)c * 16384u;
        const uint32_t Bb = sb + OFF_Bt + (uint32_t)buf * 32768u;
        uint4 v[4];
        if (c < 7) {
            load_B(0, c + 1, buf ^ 1);
            const int k1 = (c + 1) * 64;
#pragma unroll
            for (int t = 0; t < 4; t++) v[t] = *(const uint4*)(yjp[t] + k1);
        }
        mma_kk(Ab, Bb, 0);
        mma_kk(Ab, Bb, 1);
        if (c < 7) a_math(c + 1, v);
        mma_kk(Ab, Bb, 2);
        mma_kk(Ab, Bb, 3);
        if (c < 7) CP_WAIT0();
        __syncthreads();
    }

    // prefetch first B chunk of pass 1 while doing epilogue 0
    load_B(256, 0, 0);
    epilogue(0);
    CP_WAIT0();
    __syncthreads();

    // ======================= pass 1: n in [256,512) ========================
    acc_zero();
#pragma unroll 1
    for (int c = 0; c < 8; c++) {
        const int buf = c & 1;
        const uint32_t Ab = sb + OFF_A  + (uint32_t)c * 16384u;
        const uint32_t Bb = sb + OFF_Bt + (uint32_t)buf * 32768u;
        if (c < 7) load_B(256, c + 1, buf ^ 1);
        mma_kk(Ab, Bb, 0);
        mma_kk(Ab, Bb, 1);
        mma_kk(Ab, Bb, 2);
        mma_kk(Ab, Bb, 3);
        if (c < 7) CP_WAIT0();
        __syncthreads();
    }
    epilogue(256);

    // ======================= reduce + writeout =============================
#pragma unroll
    for (int x = 0; x < 8; x++) {
        part[x] += __shfl_xor_sync(0xffffffffu, part[x], 1);
        part[x] += __shfl_xor_sync(0xffffffffu, part[x], 2);
    }
    if ((lane & 3) == 0) {
#pragma unroll
        for (int mf = 0; mf < 4; mf++)
#pragma unroll
            for (int hh = 0; hh < 2; hh++) {
                int m = mw * 64 + mf * 16 + hh * 8 + (lane >> 2);
                red[nw * 128 + m] = part[mf * 2 + hh];
            }
    }
    __syncthreads();

    if (tid < 128) {
        float s = red[tid] + red[128 + tid] + red[256 + tid] + red[384 + tid]
                + b3g[0];
        int j = j0 + tid;
        out[(size_t)i * NB + j] = (j == i) ? -20.0f : s;
    }
}

// ============================================================================
// kernel_launch
// ============================================================================
extern "C" void kernel_launch(void* const* d_in, const int* in_sizes, int n_in,
                              void* d_out, int out_size) {
    const float* h  = (const float*)d_in[0];
    const float* W1 = (const float*)d_in[1];
    const float* b1 = (const float*)d_in[2];
    const float* W2 = (const float*)d_in[3];
    const float* b2 = (const float*)d_in[4];
    const float* W3 = (const float*)d_in[5];
    const float* b3 = (const float*)d_in[6];
    float* out = (float*)d_out;

    k_gemm1<<<dim3(NH / 64, NB / 32, 2), 128>>>(h, W1, b1);
    k_w2half<<<dim3(NH / 32, NH / 32), dim3(32, 32)>>>(W2);

    cudaFuncSetAttribute((const void*)pairwise_main,
                         cudaFuncAttributeMaxDynamicSharedMemorySize, SMEM_TOTAL);
    pairwise_main<<<dim3(4, NB), 256, SMEM_TOTAL>>>(b2, W3, b3, out);
}

// round 17
// speedup vs baseline: 1.7072x; 1.0554x over previous
#include <cuda_runtime.h>
#include <cuda_fp16.h>
#include <cstdint>

// ============================================================================
// B=512, D=256, H=512
//   yi = h@W1[:D]+b1 ; yj = h@W1[D:]
//   x = tanh(yi[i]+yj[j]); z = tanh(x@W2+b2); logits = z@W3+b3, diag=-20
// compute_103 PTX target (no 'a') -> tcgen05 unavailable; baseline
// mma.sync.m16n8k16 + ldmatrix + cp.async.
// R17: k_gemm1 cp.async double-buffered (was 18.7us with per-iter exposed
//      LDG latency); pass-1 B loads made pair-local with named barriers
//      (kills 8 block-wide syncs, decouples warp pairs).
// ============================================================================

#define NB 512
#define ND 256
#define NH 512

// -------------------- device scratch ----------------------------------------
__device__ __align__(16) __half g_yih[NB * NH];     // yi + b1 folded, fp16
__device__ __align__(16) __half g_yjh[NB * NH];     // yj, fp16
__device__ __align__(16) __half g_w2h[NH * NH];     // W2h[n][k] = (half)W2[k][n]

// -------------------- helpers -----------------------------------------------
__device__ __forceinline__ uint32_t smem_u32(const void* p) {
    uint32_t a;
    asm("{ .reg .u64 t; cvta.to.shared.u64 t, %1; cvt.u32.u64 %0, t; }"
        : "=r"(a) : "l"(p));
    return a;
}

#define SWZ(o) ((o) ^ (((o) >> 3) & 0x70))

#define LDSM4(r, addr) \
    asm volatile("ldmatrix.sync.aligned.m8n8.x4.shared.b16 {%0,%1,%2,%3}, [%4];" \
                 : "=r"((r)[0]), "=r"((r)[1]), "=r"((r)[2]), "=r"((r)[3]) \
                 : "r"(addr))

#define MMA16816(d, a, b0, b1) \
    asm volatile("mma.sync.aligned.m16n8k16.row.col.f32.f16.f16.f32 " \
                 "{%0,%1,%2,%3}, {%4,%5,%6,%7}, {%8,%9}, {%0,%1,%2,%3};" \
                 : "+f"((d)[0]), "+f"((d)[1]), "+f"((d)[2]), "+f"((d)[3]) \
                 : "r"((a)[0]), "r"((a)[1]), "r"((a)[2]), "r"((a)[3]), \
                   "r"(b0), "r"(b1))

#define CP_ASYNC16(dst, src) \
    asm volatile("cp.async.cg.shared.global [%0], [%1], 16;" :: "r"(dst), "l"(src))
#define CP_COMMIT()  asm volatile("cp.async.commit_group;" ::: "memory")
#define CP_WAIT0()   asm volatile("cp.async.wait_group 0;" ::: "memory")
#define CP_WAIT1()   asm volatile("cp.async.wait_group 1;" ::: "memory")

// Named barrier over 64 threads (one warp pair), ids 1..4.
#define PAIR_BAR(id) \
    asm volatile("bar.sync %0, 64;" :: "r"(id) : "memory")

// Single-MUFU fp32 tanh approximation (epilogue).
__device__ __forceinline__ float ftanh_fast(float x) {
    float y;
    asm("tanh.approx.f32 %0, %1;" : "=f"(y) : "f"(x));
    return y;
}

// tanh(a + b) on packed half2: one HADD2 + one MUFU for two elements (A tile).
__device__ __forceinline__ uint32_t htanh_add2(uint32_t a, uint32_t b) {
    uint32_t s, y;
    asm("add.rn.f16x2 %0, %1, %2;" : "=r"(s) : "r"(a), "r"(b));
    asm("tanh.approx.f16x2 %0, %1;" : "=r"(y) : "r"(s));
    return y;
}

// ============================================================================
// Stage A1: yi = h@W1[:D]+b1 (z=0), yj = h@W1[D:] (z=1), fp16 output.
// 32x64 tile, 128 threads, 4x4 per thread, cp.async double-buffered K loop.
// grid (8,16,2) = 256 CTAs.
// ============================================================================
__global__ __launch_bounds__(128)
void k_gemm1(const float* __restrict__ h, const float* __restrict__ W1,
             const float* __restrict__ b1) {
    __shared__ float As[2][32][20];   // [buf][row][k], 80B rows (16B-aligned)
    __shared__ float Bs[2][16][64];   // [buf][k][col]
    const int t    = threadIdx.x;
    const int tx   = t & 15;       // col group
    const int ty   = t >> 4;       // row group (0..7)
    const int row0 = blockIdx.y * 32;
    const int col0 = blockIdx.x * 64;
    const int base = blockIdx.z * ND;

    // A-load: 32 rows x 16B, one cp.async per thread
    const int ar = t >> 2, aq = t & 3;
    // B-load: 16 k-rows x 256B, two cp.async per thread
    const int bk = t >> 4, bc = (t & 15) * 4;

    const uint32_t a_dst[2] = {
        smem_u32(&As[0][ar][aq * 4]), smem_u32(&As[1][ar][aq * 4])};
    const uint32_t b_dst0[2] = {
        smem_u32(&Bs[0][bk][bc]), smem_u32(&Bs[1][bk][bc])};
    const uint32_t b_dst1[2] = {
        smem_u32(&Bs[0][bk + 8][bc]), smem_u32(&Bs[1][bk + 8][bc])};

    auto load = [&](int kt, int buf) {
        CP_ASYNC16(a_dst[buf], h + (size_t)(row0 + ar) * ND + kt + aq * 4);
        CP_ASYNC16(b_dst0[buf], W1 + (size_t)(base + kt + bk) * NH + col0 + bc);
        CP_ASYNC16(b_dst1[buf], W1 + (size_t)(base + kt + bk + 8) * NH + col0 + bc);
        CP_COMMIT();
    };

    float acc[4][4];
#pragma unroll
    for (int b = 0; b < 4; b++)
        acc[0][b] = (blockIdx.z == 0) ? b1[col0 + tx * 4 + b] : 0.0f;
#pragma unroll
    for (int a = 1; a < 4; a++)
#pragma unroll
        for (int b = 0; b < 4; b++) acc[a][b] = acc[0][b];

    load(0, 0);

#pragma unroll 1
    for (int it = 0; it < 16; it++) {
        const int buf = it & 1;
        if (it < 15) {
            load((it + 1) * 16, buf ^ 1);
            CP_WAIT1();
        } else {
            CP_WAIT0();
        }
        __syncthreads();
#pragma unroll
        for (int k = 0; k < 16; k++) {
            float A0 = As[buf][ty * 4 + 0][k];
            float A1 = As[buf][ty * 4 + 1][k];
            float A2 = As[buf][ty * 4 + 2][k];
            float A3 = As[buf][ty * 4 + 3][k];
            float4 rb = *(const float4*)&Bs[buf][k][tx * 4];
            float Bv[4] = {rb.x, rb.y, rb.z, rb.w};
#pragma unroll
            for (int b = 0; b < 4; b++) {
                acc[0][b] = fmaf(A0, Bv[b], acc[0][b]);
                acc[1][b] = fmaf(A1, Bv[b], acc[1][b]);
                acc[2][b] = fmaf(A2, Bv[b], acc[2][b]);
                acc[3][b] = fmaf(A3, Bv[b], acc[3][b]);
            }
        }
        __syncthreads();
    }

    __half* dst = (blockIdx.z ? g_yjh : g_yih);
#pragma unroll
    for (int a = 0; a < 4; a++) {
        __half2 lo = __floats2half2_rn(acc[a][0], acc[a][1]);
        __half2 hi = __floats2half2_rn(acc[a][2], acc[a][3]);
        __half2* p = (__half2*)(dst + (size_t)(row0 + ty * 4 + a) * NH + col0 + tx * 4);
        p[0] = lo;
        p[1] = hi;
    }
}

// ============================================================================
// Stage A2: W2h[n][k] = half(W2[k][n]) — coalesced tiled transpose
// ============================================================================
__global__ void k_w2half(const float* __restrict__ W2) {
    __shared__ float t[32][33];
    int x = blockIdx.x * 32 + threadIdx.x;  // n
    int y = blockIdx.y * 32 + threadIdx.y;  // k
    t[threadIdx.y][threadIdx.x] = W2[y * NH + x];
    __syncthreads();
    int xo = blockIdx.y * 32 + threadIdx.x; // k
    int yo = blockIdx.x * 32 + threadIdx.y; // n
    g_w2h[yo * NH + xo] = __float2half_rn(t[threadIdx.x][threadIdx.y]);
}

// ============================================================================
// Main fused kernel.
// grid = (4 j-blocks, 512 i). CTA: M=128(j) x N=512(n, two passes) x K=512.
// 256 threads / 8 warps; warp tile 64x64 (mw=w&1, nw=w>>1). A tile resident
// for all K=512 (computed once, pass 0). Pass 0: block-wide B loads + block
// syncs (A production needs them anyway). Pass 1: pair-local B loads +
// named barriers (warp pair nw loads exactly the 64 B-rows it consumes).
// ============================================================================
static constexpr int OFF_C1  = 0;        // 512 half = 1KB
static constexpr int OFF_B2  = 2048;     // 512 f32
static constexpr int OFF_W3  = 4096;     // 512 f32
static constexpr int OFF_RED = 6144;     // 512 f32
static constexpr int OFF_A   = 8192;     // 8 chunks x 128 rows x 128B = 128 KB
static constexpr int OFF_Bt  = 139264;   // 2 x 256 rows x 128B = 64 KB
static constexpr int SMEM_TOTAL = 204800;

__global__ void __launch_bounds__(256, 1)
pairwise_main(const float* __restrict__ b2g, const float* __restrict__ w3g,
              const float* __restrict__ b3g, float* __restrict__ out) {
    extern __shared__ __align__(1024) char smem[];
    const uint32_t sb = smem_u32(smem);
    const int tid  = threadIdx.x;
    const int lane = tid & 31;
    const int w    = tid >> 5;
    const int mw   = w & 1;           // 0..1  (64-row half)
    const int nw   = w >> 1;          // 0..3  (64-col quarter) == pair id
    const int i    = blockIdx.y;
    const int j0   = blockIdx.x * 128;

    __half* c1h = (__half*)(smem + OFF_C1);
    float* b2s = (float*)(smem + OFF_B2);
    float* w3s = (float*)(smem + OFF_W3);
    float* red = (float*)(smem + OFF_RED);

    for (int k = tid; k < NH; k += 256) {
        c1h[k] = g_yih[i * NH + k];
        b2s[k] = b2g[k];
        w3s[k] = w3g[k];
    }
    __syncthreads();

    // per-thread A production coords: 4 rows x 8 halves (16B) each
    const int a_q = tid & 7;                    // 16B unit within 128B row
    int a_r[4];
    const __half* yjp[4];
    uint32_t a_sw[4];
#pragma unroll
    for (int t = 0; t < 4; t++) {
        a_r[t] = (tid + t * 256) >> 3;          // rows 0..127
        yjp[t] = g_yjh + (size_t)(j0 + a_r[t]) * NH + a_q * 8;
        a_sw[t] = SWZ((uint32_t)(a_r[t] * 128 + a_q * 16));
    }

    // Block-wide B load (pass 0)
    auto load_B = [&](int nb0, int c, int buf) {
        const uint32_t base = sb + OFF_Bt + (uint32_t)buf * 32768u;
        const int k0 = c * 64;
#pragma unroll
        for (int t = 0; t < 8; t++) {
            int idx = tid + t * 256;
            int n = idx >> 3, q = idx & 7;
            uint32_t dst = base + SWZ((uint32_t)(n * 128 + q * 16));
            CP_ASYNC16(dst, g_w2h + (size_t)(nb0 + n) * NH + k0 + q * 8);
        }
        CP_COMMIT();
    };

    // Pair-local B load (pass 1, nb0=256): pair nw loads rows [nw*64, nw*64+64)
    const int plt = tid & 63;   // thread index within pair
    auto load_B_pair = [&](int c, int buf) {
        const uint32_t base = sb + OFF_Bt + (uint32_t)buf * 32768u;
        const int k0 = c * 64;
#pragma unroll
        for (int t = 0; t < 8; t++) {
            int idx = plt + t * 64;               // 0..511
            int n = nw * 64 + (idx >> 3), q = idx & 7;
            uint32_t dst = base + SWZ((uint32_t)(n * 128 + q * 16));
            CP_ASYNC16(dst, g_w2h + (size_t)(256 + n) * NH + k0 + q * 8);
        }
        CP_COMMIT();
    };

    // A math: v[t] = 8 yj halves for row a_r[t]; c = chunk index
    auto a_math = [&](int c, const uint4* v) {
        const int k0 = c * 64;
        char* base = smem + OFF_A + c * 16384;
        const uint32_t* cc = (const uint32_t*)(c1h + k0 + a_q * 8);  // 4 half2
        uint32_t c0 = cc[0], c1v = cc[1], c2v = cc[2], c3v = cc[3];
#pragma unroll
        for (int t = 0; t < 4; t++) {
            uint4 pk;
            pk.x = htanh_add2(v[t].x, c0);
            pk.y = htanh_add2(v[t].y, c1v);
            pk.z = htanh_add2(v[t].z, c2v);
            pk.w = htanh_add2(v[t].w, c3v);
            *(uint4*)(base + a_sw[t]) = pk;
        }
    };

    // ---- accumulators + lane-constant ldmatrix addressing ----
    float acc[4][8][4];
    float part[8];
#pragma unroll
    for (int x = 0; x < 8; x++) part[x] = 0.0f;

    const uint32_t a_row = (uint32_t)(mw * 64 + (lane & 15));
    const uint32_t a_col = (uint32_t)(((lane >> 4) & 1) * 16);
    const uint32_t b_row = (uint32_t)(nw * 64 + ((lane >> 4) & 1) * 8 + (lane & 7));
    const uint32_t b_col = (uint32_t)(((lane >> 3) & 1) * 16);

    auto acc_zero = [&]() {
#pragma unroll
        for (int a = 0; a < 4; a++)
#pragma unroll
            for (int b = 0; b < 8; b++)
#pragma unroll
                for (int c2 = 0; c2 < 4; c2++) acc[a][b][c2] = 0.0f;
    };

    auto mma_kk = [&](uint32_t Ab, uint32_t Bb, int kk) {
        uint32_t afr[4][4], bfr[4][4];
#pragma unroll
        for (int mf = 0; mf < 4; mf++) {
            uint32_t byte = (a_row + mf * 16) * 128 + kk * 32 + a_col;
            LDSM4(afr[mf], Ab + SWZ(byte));
        }
#pragma unroll
        for (int np = 0; np < 4; np++) {
            uint32_t byte = (b_row + np * 16) * 128 + kk * 32 + b_col;
            LDSM4(bfr[np], Bb + SWZ(byte));
        }
#pragma unroll
        for (int mf = 0; mf < 4; mf++)
#pragma unroll
            for (int np = 0; np < 4; np++) {
                MMA16816(acc[mf][2 * np],     afr[mf], bfr[np][0], bfr[np][1]);
                MMA16816(acc[mf][2 * np + 1], afr[mf], bfr[np][2], bfr[np][3]);
            }
    };

    // epilogue pass: z = tanh.approx.f32(u + b2), part += z . W3 (n-half nb0)
    auto epilogue = [&](int nb0) {
#pragma unroll
        for (int mf = 0; mf < 4; mf++)
#pragma unroll
            for (int nf = 0; nf < 8; nf++)
#pragma unroll
                for (int c2 = 0; c2 < 4; c2++) {
                    int n = nb0 + nw * 64 + nf * 8 + ((lane & 3) << 1) + (c2 & 1);
                    float u = acc[mf][nf][c2] + b2s[n];
                    part[mf * 2 + (c2 >> 1)] =
                        fmaf(ftanh_fast(u), w3s[n], part[mf * 2 + (c2 >> 1)]);
                }
    };

    // ======================= pass 0: n in [0,256) ==========================
    acc_zero();
    load_B(0, 0, 0);
    {
        uint4 v[4];
#pragma unroll
        for (int t = 0; t < 4; t++) v[t] = *(const uint4*)(yjp[t]);
        a_math(0, v);
    }
    CP_WAIT0();
    __syncthreads();

#pragma unroll 1
    for (int c = 0; c < 8; c++) {
        const int buf = c & 1;
        const uint32_t Ab = sb + OFF_A  + (uint32_t)c * 16384u;
        const uint32_t Bb = sb + OFF_Bt + (uint32_t)buf * 32768u;
        uint4 v[4];
        if (c < 7) {
            load_B(0, c + 1, buf ^ 1);
            const int k1 = (c + 1) * 64;
#pragma unroll
            for (int t = 0; t < 4; t++) v[t] = *(const uint4*)(yjp[t] + k1);
        }
        mma_kk(Ab, Bb, 0);
        mma_kk(Ab, Bb, 1);
        if (c < 7) a_math(c + 1, v);
        mma_kk(Ab, Bb, 2);
        mma_kk(Ab, Bb, 3);
        if (c < 7) CP_WAIT0();
        __syncthreads();
    }

    // prefetch first pass-1 B chunk (pair-local) while doing epilogue 0
    load_B_pair(0, 0);
    epilogue(0);
    CP_WAIT0();
    PAIR_BAR(nw + 1);

    // ======================= pass 1: n in [256,512) ========================
    acc_zero();
#pragma unroll 1
    for (int c = 0; c < 8; c++) {
        const int buf = c & 1;
        const uint32_t Ab = sb + OFF_A  + (uint32_t)c * 16384u;
        const uint32_t Bb = sb + OFF_Bt + (uint32_t)buf * 32768u;
        if (c < 7) load_B_pair(c + 1, buf ^ 1);
        mma_kk(Ab, Bb, 0);
        mma_kk(Ab, Bb, 1);
        mma_kk(Ab, Bb, 2);
        mma_kk(Ab, Bb, 3);
        if (c < 7) {
            CP_WAIT0();
            PAIR_BAR(nw + 1);
        }
    }
    epilogue(256);

    // ======================= reduce + writeout =============================
#pragma unroll
    for (int x = 0; x < 8; x++) {
        part[x] += __shfl_xor_sync(0xffffffffu, part[x], 1);
        part[x] += __shfl_xor_sync(0xffffffffu, part[x], 2);
    }
    if ((lane & 3) == 0) {
#pragma unroll
        for (int mf = 0; mf < 4; mf++)
#pragma unroll
            for (int hh = 0; hh < 2; hh++) {
                int m = mw * 64 + mf * 16 + hh * 8 + (lane >> 2);
                red[nw * 128 + m] = part[mf * 2 + hh];
            }
    }
    __syncthreads();

    if (tid < 128) {
        float s = red[tid] + red[128 + tid] + red[256 + tid] + red[384 + tid]
                + b3g[0];
        int j = j0 + tid;
        out[(size_t)i * NB + j] = (j == i) ? -20.0f : s;
    }
}

// ============================================================================
// kernel_launch
// ============================================================================
extern "C" void kernel_launch(void* const* d_in, const int* in_sizes, int n_in,
                              void* d_out, int out_size) {
    const float* h  = (const float*)d_in[0];
    const float* W1 = (const float*)d_in[1];
    const float* b1 = (const float*)d_in[2];
    const float* W2 = (const float*)d_in[3];
    const float* b2 = (const float*)d_in[4];
    const float* W3 = (const float*)d_in[5];
    const float* b3 = (const float*)d_in[6];
    float* out = (float*)d_out;

    k_gemm1<<<dim3(NH / 64, NB / 32, 2), 128>>>(h, W1, b1);
    k_w2half<<<dim3(NH / 32, NH / 32), dim3(32, 32)>>>(W2);

    cudaFuncSetAttribute((const void*)pairwise_main,
                         cudaFuncAttributeMaxDynamicSharedMemorySize, SMEM_TOTAL);
    pairwise_main<<<dim3(4, NB), 256, SMEM_TOTAL>>>(b2, W3, b3, out);
}